// round 10
// baseline (speedup 1.0000x reference)
#include <cuda_runtime.h>
#include <cuda_bf16.h>
#include <cuda_fp16.h>
#include <cstdint>

#define BB 4
#define SS 1025
#define SQ 1024
#define EE 1024
#define HH 16
#define DH 64
#define BH (BB*HH)
#define EPSF 1e-5f
#define MROWS_OUT (BB*SS)     // 4100
#define MTILES_OUT 33         // 33*128 = 4224

typedef __nv_bfloat16 bf16;

// ---------------- device scratch (allocation-free) ----------------
__device__ float QS[BH*SQ*DH];          // fp32 q  (qstats)
__device__ float KS[BH*SQ*DH];          // fp32 k  (cls path)
__device__ float VS[BH*SQ*DH];          // fp32 v  (cls path)
__device__ __half Xh[BB*SS*EE];                       // x single fp16
__device__ __half WqHh[EE*EE], WqLh[EE*EE];           // 64*W fp16 hi/lo
__device__ __half WkHh[EE*EE], WkLh[EE*EE];
__device__ __half WvHh[EE*EE], WvLh[EE*EE];
__device__ __half WcHh[EE*EE], WcLh[EE*EE];
__device__ __half WoHh[EE*EE], WoLh[EE*EE];
__device__ __half Qh[BH*SQ*DH];                       // q single fp16
__device__ __half Khh[BH*SQ*DH], Klh[BH*SQ*DH];       // k fp16 hi/lo
__device__ __half VTHh[BH*DH*SQ], VTLh[BH*DH*SQ];     // (16*V)^T hi/lo
__device__ __half CPTHh[BH*DH*SQ], CPTLh[BH*DH*SQ];   // (16*CP)^T hi/lo
__device__ __half VALSh[(size_t)MTILES_OUT*128*EE];   // values, single fp16
__device__ float CVEC[BH*DH];
__device__ float CN2[BH];
__device__ float QN2[BH*SQ];
__device__ float CQg[BH*SQ];

// ---------------- warp-mma helpers ----------------
__device__ __forceinline__ uint32_t s2u(const void* p) {
    uint32_t a;
    asm("{ .reg .u64 t; cvta.to.shared.u64 t, %1; cvt.u32.u64 %0, t; }" : "=r"(a) : "l"(p));
    return a;
}
#define LDSM4(R0,R1,R2,R3,addr) \
    asm volatile("ldmatrix.sync.aligned.m8n8.x4.shared.b16 {%0,%1,%2,%3}, [%4];" \
        : "=r"(R0),"=r"(R1),"=r"(R2),"=r"(R3) : "r"(addr))

__device__ __forceinline__ void mma16816h(float* c, uint32_t a0, uint32_t a1,
                                          uint32_t a2, uint32_t a3,
                                          uint32_t b0, uint32_t b1) {
    asm volatile(
        "mma.sync.aligned.m16n8k16.row.col.f32.f16.f16.f32 "
        "{%0,%1,%2,%3}, {%4,%5,%6,%7}, {%8,%9}, {%0,%1,%2,%3};"
        : "+f"(c[0]), "+f"(c[1]), "+f"(c[2]), "+f"(c[3])
        : "r"(a0), "r"(a1), "r"(a2), "r"(a3), "r"(b0), "r"(b1));
}

// fp16 2-pass k16 step: A single, B hi/lo. MT*16 x 32 warp tile, pass-ordered.
template<int MT>
__device__ __forceinline__ void wmma_step2h(float (*acc)[4][4],
    uint32_t aB, uint32_t bHb, uint32_t bLb,
    int mrow0, int ncol0, int k0, int lane)
{
    uint32_t aF[MT][4];
    #pragma unroll
    for (int mi = 0; mi < MT; mi++) {
        uint32_t off = ((uint32_t)(mrow0 + mi*16 + (lane & 15))*40u + (uint32_t)k0 + ((lane >> 4) << 3)) * 2u;
        LDSM4(aF[mi][0], aF[mi][1], aF[mi][2], aF[mi][3], aB + off);
    }
    uint32_t bHf[4][2], bLf[4][2];
    int j = lane >> 3;
    #pragma unroll
    for (int p = 0; p < 2; p++) {
        uint32_t off = ((uint32_t)(ncol0 + p*16 + ((j >> 1) << 3) + (lane & 7))*40u + (uint32_t)k0 + ((j & 1) << 3)) * 2u;
        uint32_t r0, r1, r2, r3;
        LDSM4(r0, r1, r2, r3, bHb + off);
        bHf[p*2][0] = r0; bHf[p*2][1] = r1; bHf[p*2+1][0] = r2; bHf[p*2+1][1] = r3;
        LDSM4(r0, r1, r2, r3, bLb + off);
        bLf[p*2][0] = r0; bLf[p*2][1] = r1; bLf[p*2+1][0] = r2; bLf[p*2+1][1] = r3;
    }
    #pragma unroll
    for (int mi = 0; mi < MT; mi++)
        #pragma unroll
        for (int nj = 0; nj < 4; nj++)
            mma16816h(acc[mi][nj], aF[mi][0], aF[mi][1], aF[mi][2], aF[mi][3], bHf[nj][0], bHf[nj][1]);
    #pragma unroll
    for (int mi = 0; mi < MT; mi++)
        #pragma unroll
        for (int nj = 0; nj < 4; nj++)
            mma16816h(acc[mi][nj], aF[mi][0], aF[mi][1], aF[mi][2], aF[mi][3], bLf[nj][0], bLf[nj][1]);
}

// 4 n8-frags (32 cols) from smem tile (stride 40)
__device__ __forceinline__ void ldB32(uint32_t (*bf)[2], uint32_t base, int n0_, int k0, int lane) {
    int j = lane >> 3;
    #pragma unroll
    for (int p = 0; p < 2; p++) {
        uint32_t off = ((uint32_t)(n0_ + p*16 + ((j >> 1) << 3) + (lane & 7))*40u + (uint32_t)k0 + ((j & 1) << 3)) * 2u;
        uint32_t r0, r1, r2, r3;
        LDSM4(r0, r1, r2, r3, base + off);
        bf[p*2][0] = r0; bf[p*2][1] = r1; bf[p*2+1][0] = r2; bf[p*2+1][1] = r3;
    }
}

// load nrows x 32 b16 elems into smem tile (stride 40 elems) via cp.async
__device__ __forceinline__ void ld_tile32(uint32_t sdst, const void* gv, size_t rstride, int nrows) {
    const __half* g = (const __half*)gv;
    int tid = threadIdx.x;
    int tot = nrows * 4;
    for (int u = tid; u < tot; u += 256) {
        int r = u >> 2, c = u & 3;
        uint32_t dst = sdst + (uint32_t)(r*80 + c*16);
        const __half* src = g + (size_t)r * rstride + (c << 3);
        asm volatile("cp.async.cg.shared.global [%0], [%1], 16;" :: "r"(dst), "l"(src) : "memory");
    }
}
#define CPA_COMMIT() asm volatile("cp.async.commit_group;" ::: "memory")
#define CPA_WAIT1()  asm volatile("cp.async.wait_group 1;" ::: "memory")
#define CPA_WAIT0()  asm volatile("cp.async.wait_group 0;" ::: "memory")

__device__ __forceinline__ void split2h(float v, __half& h, __half& l) {
    h = __float2half(v);
    l = __float2half(v - __half2float(h));
}
__device__ __forceinline__ uint32_t packh2(float a, float b) {
    __half2 t = __floats2half2_rn(a, b);
    return *(uint32_t*)&t;
}
__device__ __forceinline__ uint32_t packh2x(__half a, __half b) {
    return (uint32_t)__half_as_ushort(a) | ((uint32_t)__half_as_ushort(b) << 16);
}

// ============================================================
// conversions
// ============================================================
__global__ void convXh_kernel(const float* __restrict__ s, __half* __restrict__ h, int n4) {
    int i = blockIdx.x * 256 + threadIdx.x;
    if (i >= n4) return;
    float4 v = ((const float4*)s)[i];
    uint2 hp;
    hp.x = packh2(v.x, v.y); hp.y = packh2(v.z, v.w);
    ((uint2*)h)[i] = hp;
}
__device__ __forceinline__ void convW_body(const float* __restrict__ s,
                                           __half* __restrict__ h,
                                           __half* __restrict__ l, int i) {
    float4 v = ((const float4*)s)[i];
    __half h0, h1, h2, h3, l0, l1, l2, l3;
    split2h(v.x*64.f, h0, l0); split2h(v.y*64.f, h1, l1);
    split2h(v.z*64.f, h2, l2); split2h(v.w*64.f, h3, l3);
    uint2 hp, lp;
    hp.x = packh2x(h0, h1); hp.y = packh2x(h2, h3);
    lp.x = packh2x(l0, l1); lp.y = packh2x(l2, l3);
    ((uint2*)h)[i] = hp;
    ((uint2*)l)[i] = lp;
}
__global__ void convW_kernel(const float* __restrict__ s, __half* __restrict__ h,
                             __half* __restrict__ l, int n4) {
    int i = blockIdx.x * 256 + threadIdx.x;
    if (i >= n4) return;
    convW_body(s, h, l, i);
}
__global__ void convW2_kernel(const float* __restrict__ s0, __half* __restrict__ h0,
                              __half* __restrict__ l0,
                              const float* __restrict__ s1, __half* __restrict__ h1,
                              __half* __restrict__ l1, int n4) {
    int i = blockIdx.x * 256 + threadIdx.x;
    if (i >= n4) return;
    if (blockIdx.y == 0) convW_body(s0, h0, l0, i);
    else                 convW_body(s1, h1, l1, i);
}

// ============================================================
// proj: 128x128 tile of (x @ (64W)^T)/64 + b. fp16 2-pass. grid(8,32,4)
// smem: 2 x 3 tiles x 10240 = 61440
// ============================================================
__global__ void __launch_bounds__(256) proj_mm(
    const float* __restrict__ b0, const float* __restrict__ b1,
    const float* __restrict__ b2, const float* __restrict__ b3)
{
    extern __shared__ uint8_t dyn[];
    uint32_t sb = s2u(dyn);
    int tid = threadIdx.x, wid = tid >> 5, lane = tid & 31;

    int w = blockIdx.z;
    const __half* WHp = (w==0)?WqHh:(w==1)?WkHh:(w==2)?WvHh:WcHh;
    const __half* WLp = (w==0)?WqLh:(w==1)?WkLh:(w==2)?WvLh:WcLh;
    const float* bias = (w==0)?b0:(w==1)?b1:(w==2)?b2:b3;

    int m0 = blockIdx.y * 128, n0 = blockIdx.x * 128;
    int b_ = m0 >> 10, i0 = m0 & 1023;

    const __half* aF = Xh + (size_t)(b_*SS + i0 + 1)*EE;
    const __half* bH = WHp + (size_t)n0*EE;
    const __half* bL = WLp + (size_t)n0*EE;

    float acc[4][4][4] = {};
    int wm = wid & 1, wn = wid >> 1;
    int mrow0 = wm*64, ncol0 = wn*32;

    ld_tile32(sb,         aF, EE, 128);
    ld_tile32(sb + 10240, bH, EE, 128);
    ld_tile32(sb + 20480, bL, EE, 128);
    CPA_COMMIT();
    int buf = 0;
    for (int ch = 0; ch < 32; ch++) {
        if (ch + 1 < 32) {
            uint32_t nb = sb + (buf^1)*30720;
            int kt = (ch + 1) * 32;
            ld_tile32(nb,         aF + kt, EE, 128);
            ld_tile32(nb + 10240, bH + kt, EE, 128);
            ld_tile32(nb + 20480, bL + kt, EE, 128);
            CPA_COMMIT();
            CPA_WAIT1();
        } else CPA_WAIT0();
        __syncthreads();
        uint32_t base = sb + buf*30720;
        wmma_step2h<4>(acc, base, base+10240, base+20480, mrow0, ncol0, 0,  lane);
        wmma_step2h<4>(acc, base, base+10240, base+20480, mrow0, ncol0, 16, lane);
        __syncthreads();
        buf ^= 1;
    }

    int rbase = mrow0 + (lane >> 2);
    int cbase = ncol0 + (lane & 3)*2;
    const float inv64 = 1.0f/64.0f;
    #pragma unroll
    for (int mi = 0; mi < 4; mi++)
        #pragma unroll
        for (int half = 0; half < 2; half++) {
            int i = i0 + rbase + mi*16 + half*8;
            #pragma unroll
            for (int nj = 0; nj < 4; nj++) {
                int col = n0 + cbase + nj*8;
                int h2 = col >> 6, d2 = col & 63;
                float v0 = acc[mi][nj][half*2]*inv64   + bias[col];
                float v1 = acc[mi][nj][half*2+1]*inv64 + bias[col+1];
                size_t qi = ((size_t)(b_*HH + h2)*SQ + i)*DH + d2;
                size_t ti = ((size_t)(b_*HH + h2)*DH + d2)*SQ + i;
                if (w == 0) {
                    *(float2*)&QS[qi] = make_float2(v0, v1);
                    *(uint32_t*)&Qh[qi] = packh2(v0, v1);
                } else if (w == 1) {
                    *(float2*)&KS[qi] = make_float2(v0, v1);
                    __half h0v, l0v, h1v, l1v;
                    split2h(v0, h0v, l0v); split2h(v1, h1v, l1v);
                    *(uint32_t*)&Khh[qi] = packh2x(h0v, h1v);
                    *(uint32_t*)&Klh[qi] = packh2x(l0v, l1v);
                } else if (w == 2) {
                    *(float2*)&VS[qi] = make_float2(v0, v1);
                    __half h0v, l0v, h1v, l1v;
                    split2h(v0*16.f, h0v, l0v); split2h(v1*16.f, h1v, l1v);
                    VTHh[ti] = h0v;      VTLh[ti] = l0v;
                    VTHh[ti + SQ] = h1v; VTLh[ti + SQ] = l1v;
                } else {
                    __half h0v, l0v, h1v, l1v;
                    split2h(v0*16.f, h0v, l0v); split2h(v1*16.f, h1v, l1v);
                    CPTHh[ti] = h0v;      CPTLh[ti] = l0v;
                    CPTHh[ti + SQ] = h1v; CPTLh[ti + SQ] = l1v;
                }
            }
        }
}

// ============================================================
// fused attention: S = Qh·K(hi/lo) fp16 2-pass -> raw l to attn,
// dual online softmax, O1 += P1@V, O2 += P2@CP (fp16 2-pass), then
// in-kernel normalization of this block's attn slice. grid(8,64) block 256
// smem: Q 20480 + 2 x 61440 = 143360
// ============================================================
__global__ void __launch_bounds__(256) fused_attn(float* __restrict__ attn)
{
    extern __shared__ uint8_t dyn[];
    uint32_t sQ = s2u(dyn);
    uint32_t sT = sQ + 20480;
    int tid = threadIdx.x, wid = tid >> 5, lane = tid & 31;
    int bh = blockIdx.y;
    int m0 = blockIdx.x * 128;
    int mrow0 = wid * 16;
    int g = lane >> 2, tig = lane & 3;
    int r0 = mrow0 + g, r1 = r0 + 8;
    int gr0 = m0 + r0, gr1 = m0 + r1;

    float qn0 = QN2[(size_t)bh*SQ + gr0], qn1 = QN2[(size_t)bh*SQ + gr1];
    float cn = CN2[bh];
    float sc0 = rsqrtf(64.0f * qn0), sc1r = rsqrtf(64.0f * qn1);
    float rr0 = rsqrtf(qn0 * cn), rr1 = rsqrtf(qn1 * cn);

    float* attnb = attn + (size_t)bh*SQ*SQ;
    const float* cqrow = CQg + (size_t)bh*SQ;

    {
        const __half* qh = Qh + (size_t)bh*SQ*DH + (size_t)m0*DH;
        ld_tile32(sQ,         qh,      DH, 128);
        ld_tile32(sQ + 10240, qh + 32, DH, 128);
        CPA_COMMIT();
    }

    #define FLOAD(bb, jt) do { \
        int j0_ = (jt) * 64; \
        const __half* kh_ = Khh + (size_t)bh*SQ*DH + (size_t)j0_*DH; \
        const __half* kl_ = Klh + (size_t)bh*SQ*DH + (size_t)j0_*DH; \
        const __half* vh_ = VTHh + (size_t)bh*DH*SQ + j0_; \
        const __half* vl_ = VTLh + (size_t)bh*DH*SQ + j0_; \
        const __half* ph_ = CPTHh + (size_t)bh*DH*SQ + j0_; \
        const __half* pl_ = CPTLh + (size_t)bh*DH*SQ + j0_; \
        ld_tile32((bb),        kh_,      DH, 64); \
        ld_tile32((bb)+5120,   kh_ + 32, DH, 64); \
        ld_tile32((bb)+10240,  kl_,      DH, 64); \
        ld_tile32((bb)+15360,  kl_ + 32, DH, 64); \
        ld_tile32((bb)+20480,  vh_,      SQ, 64); \
        ld_tile32((bb)+25600,  vh_ + 32, SQ, 64); \
        ld_tile32((bb)+30720,  vl_,      SQ, 64); \
        ld_tile32((bb)+35840,  vl_ + 32, SQ, 64); \
        ld_tile32((bb)+40960,  ph_,      SQ, 64); \
        ld_tile32((bb)+46080,  ph_ + 32, SQ, 64); \
        ld_tile32((bb)+51200,  pl_,      SQ, 64); \
        ld_tile32((bb)+56320,  pl_ + 32, SQ, 64); \
        CPA_COMMIT(); \
    } while (0)

    float O1[8][4] = {}, O2[8][4] = {};
    float m1_0 = -1e30f, m1_1 = -1e30f, m2_0 = -1e30f, m2_1 = -1e30f;
    float s1_0 = 0.f, s1_1 = 0.f, s2_0 = 0.f, s2_1 = 0.f;

    FLOAD(sT, 0);
    int buf = 0;
    for (int jt = 0; jt < 16; jt++) {
        if (jt + 1 < 16) { FLOAD(sT + (buf^1)*61440, jt + 1); CPA_WAIT1(); }
        else CPA_WAIT0();
        __syncthreads();
        uint32_t bb = sT + buf*61440;
        int j0 = jt * 64;

        // ---- S = Qh · K (fp16 2-pass) ----
        float S[8][4] = {};
        #pragma unroll
        for (int kk = 0; kk < 64; kk += 16) {
            int cch = kk >> 5, k0 = kk & 16;
            uint32_t aQ = sQ + cch*10240;
            uint32_t a0, a1, a2, a3;
            uint32_t offA = ((uint32_t)(mrow0 + (lane & 15))*40u + (uint32_t)k0 + ((lane >> 4) << 3)) * 2u;
            LDSM4(a0, a1, a2, a3, aQ + offA);
            uint32_t bHf[4][2], bLf[4][2], bHf2[4][2], bLf2[4][2];
            uint32_t kbH = bb + cch*5120, kbL = bb + 10240 + cch*5120;
            ldB32(bHf,  kbH, 0,  k0, lane);
            ldB32(bHf2, kbH, 32, k0, lane);
            ldB32(bLf,  kbL, 0,  k0, lane);
            ldB32(bLf2, kbL, 32, k0, lane);
            #pragma unroll
            for (int f = 0; f < 4; f++) {
                mma16816h(S[f],   a0, a1, a2, a3, bHf[f][0],  bHf[f][1]);
                mma16816h(S[f+4], a0, a1, a2, a3, bHf2[f][0], bHf2[f][1]);
            }
            #pragma unroll
            for (int f = 0; f < 4; f++) {
                mma16816h(S[f],   a0, a1, a2, a3, bLf[f][0],  bLf[f][1]);
                mma16816h(S[f+4], a0, a1, a2, a3, bLf2[f][0], bLf2[f][1]);
            }
        }

        // ---- scale to l, store raw, track maxes ----
        float cqv[8][2];
        float lmax0 = -1e30f, lmax1 = -1e30f, l2max0 = -1e30f, l2max1 = -1e30f;
        #pragma unroll
        for (int f = 0; f < 8; f++) {
            int col = j0 + f*8 + tig*2;
            float2 cq = *(const float2*)&cqrow[col];
            cqv[f][0] = cq.x; cqv[f][1] = cq.y;
            S[f][0] *= sc0;  S[f][1] *= sc0;
            S[f][2] *= sc1r; S[f][3] *= sc1r;
            *(float2*)&attnb[(size_t)gr0*SQ + col] = make_float2(S[f][0], S[f][1]);
            *(float2*)&attnb[(size_t)gr1*SQ + col] = make_float2(S[f][2], S[f][3]);
            lmax0 = fmaxf(lmax0, fmaxf(S[f][0], S[f][1]));
            lmax1 = fmaxf(lmax1, fmaxf(S[f][2], S[f][3]));
            l2max0 = fmaxf(l2max0, fmaxf(S[f][0]*cq.x*rr0, S[f][1]*cq.y*rr0));
            l2max1 = fmaxf(l2max1, fmaxf(S[f][2]*cq.x*rr1, S[f][3]*cq.y*rr1));
        }
        #pragma unroll
        for (int o = 1; o <= 2; o <<= 1) {
            lmax0  = fmaxf(lmax0,  __shfl_xor_sync(0xffffffffu, lmax0,  o));
            lmax1  = fmaxf(lmax1,  __shfl_xor_sync(0xffffffffu, lmax1,  o));
            l2max0 = fmaxf(l2max0, __shfl_xor_sync(0xffffffffu, l2max0, o));
            l2max1 = fmaxf(l2max1, __shfl_xor_sync(0xffffffffu, l2max1, o));
        }
        float m1n0 = fmaxf(m1_0, lmax0),  m1n1 = fmaxf(m1_1, lmax1);
        float m2n0 = fmaxf(m2_0, l2max0), m2n1 = fmaxf(m2_1, l2max1);
        float f10 = __expf(m1_0 - m1n0), f11 = __expf(m1_1 - m1n1);
        float f20 = __expf(m2_0 - m2n0), f21 = __expf(m2_1 - m2n1);
        m1_0 = m1n0; m1_1 = m1n1; m2_0 = m2n0; m2_1 = m2n1;
        #pragma unroll
        for (int f = 0; f < 8; f++) {
            O1[f][0] *= f10; O1[f][1] *= f10; O1[f][2] *= f11; O1[f][3] *= f11;
            O2[f][0] *= f20; O2[f][1] *= f20; O2[f][2] *= f21; O2[f][3] *= f21;
        }

        // ---- path 1: O1 += P1 @ (16V), fp16 2-pass ----
        {
            uint32_t ph01[8], ph23[8];
            float ps0 = 0.f, ps1 = 0.f;
            #pragma unroll
            for (int f = 0; f < 8; f++) {
                float p0 = __expf(S[f][0] - m1n0), p1v = __expf(S[f][1] - m1n0);
                float p2v = __expf(S[f][2] - m1n1), p3v = __expf(S[f][3] - m1n1);
                ps0 += p0 + p1v; ps1 += p2v + p3v;
                ph01[f] = packh2(p0, p1v);
                ph23[f] = packh2(p2v, p3v);
            }
            #pragma unroll
            for (int o = 1; o <= 2; o <<= 1) {
                ps0 += __shfl_xor_sync(0xffffffffu, ps0, o);
                ps1 += __shfl_xor_sync(0xffffffffu, ps1, o);
            }
            s1_0 = s1_0 * f10 + ps0; s1_1 = s1_1 * f11 + ps1;
            #pragma unroll
            for (int kk = 0; kk < 64; kk += 16) {
                int cch = kk >> 5, k0 = kk & 16;
                int gp = kk >> 3;
                uint32_t vbH = bb + 20480 + cch*5120, vbL = bb + 30720 + cch*5120;
                uint32_t bHf[4][2], bLf[4][2], bHf2[4][2], bLf2[4][2];
                ldB32(bHf,  vbH, 0,  k0, lane);
                ldB32(bHf2, vbH, 32, k0, lane);
                ldB32(bLf,  vbL, 0,  k0, lane);
                ldB32(bLf2, vbL, 32, k0, lane);
                uint32_t a0 = ph01[gp], a1 = ph23[gp], a2 = ph01[gp+1], a3 = ph23[gp+1];
                #pragma unroll
                for (int f = 0; f < 4; f++) {
                    mma16816h(O1[f],   a0, a1, a2, a3, bHf[f][0],  bHf[f][1]);
                    mma16816h(O1[f+4], a0, a1, a2, a3, bHf2[f][0], bHf2[f][1]);
                }
                #pragma unroll
                for (int f = 0; f < 4; f++) {
                    mma16816h(O1[f],   a0, a1, a2, a3, bLf[f][0],  bLf[f][1]);
                    mma16816h(O1[f+4], a0, a1, a2, a3, bLf2[f][0], bLf2[f][1]);
                }
            }
        }

        // ---- path 2: O2 += P2 @ (16CP), fp16 2-pass ----
        {
            uint32_t ph01[8], ph23[8];
            float ps0 = 0.f, ps1 = 0.f;
            #pragma unroll
            for (int f = 0; f < 8; f++) {
                float p0 = __expf(S[f][0]*cqv[f][0]*rr0 - m2n0);
                float p1v = __expf(S[f][1]*cqv[f][1]*rr0 - m2n0);
                float p2v = __expf(S[f][2]*cqv[f][0]*rr1 - m2n1);
                float p3v = __expf(S[f][3]*cqv[f][1]*rr1 - m2n1);
                ps0 += p0 + p1v; ps1 += p2v + p3v;
                ph01[f] = packh2(p0, p1v);
                ph23[f] = packh2(p2v, p3v);
            }
            #pragma unroll
            for (int o = 1; o <= 2; o <<= 1) {
                ps0 += __shfl_xor_sync(0xffffffffu, ps0, o);
                ps1 += __shfl_xor_sync(0xffffffffu, ps1, o);
            }
            s2_0 = s2_0 * f20 + ps0; s2_1 = s2_1 * f21 + ps1;
            #pragma unroll
            for (int kk = 0; kk < 64; kk += 16) {
                int cch = kk >> 5, k0 = kk & 16;
                int gp = kk >> 3;
                uint32_t pbH = bb + 40960 + cch*5120, pbL = bb + 51200 + cch*5120;
                uint32_t bHf[4][2], bLf[4][2], bHf2[4][2], bLf2[4][2];
                ldB32(bHf,  pbH, 0,  k0, lane);
                ldB32(bHf2, pbH, 32, k0, lane);
                ldB32(bLf,  pbL, 0,  k0, lane);
                ldB32(bLf2, pbL, 32, k0, lane);
                uint32_t a0 = ph01[gp], a1 = ph23[gp], a2 = ph01[gp+1], a3 = ph23[gp+1];
                #pragma unroll
                for (int f = 0; f < 4; f++) {
                    mma16816h(O2[f],   a0, a1, a2, a3, bHf[f][0],  bHf[f][1]);
                    mma16816h(O2[f+4], a0, a1, a2, a3, bHf2[f][0], bHf2[f][1]);
                }
                #pragma unroll
                for (int f = 0; f < 4; f++) {
                    mma16816h(O2[f],   a0, a1, a2, a3, bLf[f][0],  bLf[f][1]);
                    mma16816h(O2[f+4], a0, a1, a2, a3, bLf2[f][0], bLf2[f][1]);
                }
            }
        }
        __syncthreads();
        buf ^= 1;
    }
    #undef FLOAD

    // ---- epilogue: values rows (/16 undoes V/CP scale) ----
    int b_ = bh / HH, h_ = bh % HH;
    float is10 = 0.0625f/s1_0, is11 = 0.0625f/s1_1, is20 = 0.0625f/s2_0, is21 = 0.0625f/s2_1;
    size_t ob0 = (size_t)(b_*SS + 1 + gr0)*EE + h_*DH;
    size_t ob1 = (size_t)(b_*SS + 1 + gr1)*EE + h_*DH;
    #pragma unroll
    for (int f = 0; f < 8; f++) {
        int d = f*8 + tig*2;
        float v0 = O1[f][0]*is10 + O2[f][0]*is20;
        float v1 = O1[f][1]*is10 + O2[f][1]*is20;
        float v2 = O1[f][2]*is11 + O2[f][2]*is21;
        float v3 = O1[f][3]*is11 + O2[f][3]*is21;
        *(uint32_t*)&VALSh[ob0 + d] = packh2(v0, v1);
        *(uint32_t*)&VALSh[ob1 + d] = packh2(v2, v3);
    }

    // ---- in-kernel attn normalization (L2-warm rewrite of this block's slice) ----
    float* smf = (float*)dyn;   // Q tile no longer needed
    __syncthreads();
    if (tig == 0) {
        smf[r0] = m1_0; smf[128 + r0] = 1.f/s1_0;
        smf[r1] = m1_1; smf[128 + r1] = 1.f/s1_1;
    }
    __syncthreads();
    for (int idx = tid; idx < 128*256; idx += 256) {
        int r = idx >> 8, c4 = (idx & 255) << 2;
        float m = smf[r], si = smf[128 + r];
        float4* p = (float4*)(attnb + (size_t)(m0 + r)*SQ + c4);
        float4 v = *p;
        v.x = __expf(v.x - m)*si;
        v.y = __expf(v.y - m)*si;
        v.z = __expf(v.z - m)*si;
        v.w = __expf(v.w - m)*si;
        *p = v;
    }
}

// ============================================================
// out: VALS(f16) @ (64Wo)^T/64 + bo. fp16 2-pass. grid(8,33)
// ============================================================
__global__ void __launch_bounds__(256) out_mm(const float* __restrict__ bo,
                                             float* __restrict__ out)
{
    extern __shared__ uint8_t dyn[];
    uint32_t sb = s2u(dyn);
    int tid = threadIdx.x, wid = tid >> 5, lane = tid & 31;
    int m0 = blockIdx.y * 128, n0 = blockIdx.x * 128;

    const __half* aF = VALSh + (size_t)m0*EE;
    const __half* bH = WoHh + (size_t)n0*EE;
    const __half* bL = WoLh + (size_t)n0*EE;

    float acc[4][4][4] = {};
    int wm = wid & 1, wn = wid >> 1;
    int mrow0 = wm*64, ncol0 = wn*32;

    ld_tile32(sb,         aF, EE, 128);
    ld_tile32(sb + 10240, bH, EE, 128);
    ld_tile32(sb + 20480, bL, EE, 128);
    CPA_COMMIT();
    int buf = 0;
    for (int ch = 0; ch < 32; ch++) {
        if (ch + 1 < 32) {
            uint32_t nb = sb + (buf^1)*30720;
            int kt = (ch + 1) * 32;
            ld_tile32(nb,         aF + kt, EE, 128);
            ld_tile32(nb + 10240, bH + kt, EE, 128);
            ld_tile32(nb + 20480, bL + kt, EE, 128);
            CPA_COMMIT();
            CPA_WAIT1();
        } else CPA_WAIT0();
        __syncthreads();
        uint32_t base = sb + buf*30720;
        wmma_step2h<4>(acc, base, base+10240, base+20480, mrow0, ncol0, 0,  lane);
        wmma_step2h<4>(acc, base, base+10240, base+20480, mrow0, ncol0, 16, lane);
        __syncthreads();
        buf ^= 1;
    }

    int rbase = mrow0 + (lane >> 2);
    int cbase = ncol0 + (lane & 3)*2;
    const float inv64 = 1.0f/64.0f;
    #pragma unroll
    for (int mi = 0; mi < 4; mi++)
        #pragma unroll
        for (int half = 0; half < 2; half++) {
            int mr = m0 + rbase + mi*16 + half*8;
            if (mr >= MROWS_OUT) continue;
            #pragma unroll
            for (int nj = 0; nj < 4; nj++) {
                int col = n0 + cbase + nj*8;
                *(float2*)&out[(size_t)mr*EE + col] =
                    make_float2(acc[mi][nj][half*2]*inv64 + bo[col],
                                acc[mi][nj][half*2+1]*inv64 + bo[col+1]);
            }
        }
}

// ============================================================
// cls token projection + CN2. grid BH, block 64
// ============================================================
__global__ void clsproj_kernel(const float* __restrict__ x,
                               const float* __restrict__ Wq,
                               const float* __restrict__ bq) {
    int bh = blockIdx.x;
    int b_ = bh / HH, h_ = bh % HH;
    int d  = threadIdx.x;
    int j  = h_*DH + d;
    const float* xr = x  + (size_t)(b_*SS)*EE;
    const float* wr = Wq + (size_t)j*EE;
    float s = 0.f;
    for (int e = 0; e < EE; e += 4) {
        float4 xv = *(const float4*)(xr + e);
        float4 wv = *(const float4*)(wr + e);
        s += xv.x*wv.x + xv.y*wv.y + xv.z*wv.z + xv.w*wv.w;
    }
    s += bq[j];
    CVEC[bh*DH + d] = s;
    __shared__ float red[64];
    red[d] = s*s; __syncthreads();
    for (int o = 32; o > 0; o >>= 1) { if (d < o) red[d] += red[d+o]; __syncthreads(); }
    if (d == 0) CN2[bh] = fmaxf(red[0], EPSF);
}

// ============================================================
// per-row q stats: QN2 and CQ. grid BH*SQ/8, block 256
// ============================================================
__global__ void qstats_kernel() {
    int row  = blockIdx.x*8 + (threadIdx.x >> 5);
    int lane = threadIdx.x & 31;
    int bh   = row >> 10;
    const float* qr = QS   + (size_t)row*DH;
    const float* cv = CVEC + bh*DH;
    float n2 = 0.f, cq = 0.f;
    #pragma unroll
    for (int d = lane; d < DH; d += 32) {
        float qv = qr[d];
        n2 += qv*qv;
        cq += qv*cv[d];
    }
    #pragma unroll
    for (int o = 16; o > 0; o >>= 1) {
        n2 += __shfl_xor_sync(0xffffffffu, n2, o);
        cq += __shfl_xor_sync(0xffffffffu, cq, o);
    }
    if (lane == 0) { QN2[row] = fmaxf(n2, EPSF); CQg[row] = cq; }
}

// ============================================================
// cls path: ck softmax -> cls_out row (fp16 into VALS). grid BH, block 256
// ============================================================
__global__ void cls_kernel() {
    int bh = blockIdx.x;
    int tid = threadIdx.x;
    const float* Kp = KS + (size_t)bh*SQ*DH;
    const float* Vp = VS + (size_t)bh*SQ*DH;
    __shared__ float p_s[SQ];
    __shared__ float red[256];
    __shared__ float c_s[DH];
    if (tid < DH) c_s[tid] = CVEC[bh*DH + tid];
    __syncthreads();

    float scale = rsqrtf(64.0f * CN2[bh]);
    float lo[4];
    #pragma unroll
    for (int p = 0; p < 4; p++) {
        int j = tid + p*256;
        const float* kr = Kp + (size_t)j*DH;
        float s = 0.f;
        #pragma unroll
        for (int d = 0; d < DH; d += 4) {
            float4 kv = *(const float4*)(kr + d);
            s += c_s[d]*kv.x + c_s[d+1]*kv.y + c_s[d+2]*kv.z + c_s[d+3]*kv.w;
        }
        lo[p] = s * scale;
    }
    float m = fmaxf(fmaxf(lo[0],lo[1]), fmaxf(lo[2],lo[3]));
    red[tid] = m; __syncthreads();
    #pragma unroll
    for (int o = 128; o > 0; o >>= 1) { if (tid < o) red[tid] = fmaxf(red[tid], red[tid+o]); __syncthreads(); }
    m = red[0]; __syncthreads();
    float e[4], s = 0.f;
    #pragma unroll
    for (int p = 0; p < 4; p++) { e[p] = __expf(lo[p] - m); s += e[p]; }
    red[tid] = s; __syncthreads();
    #pragma unroll
    for (int o = 128; o > 0; o >>= 1) { if (tid < o) red[tid] += red[tid+o]; __syncthreads(); }
    float inv = 1.0f / red[0]; __syncthreads();
    #pragma unroll
    for (int p = 0; p < 4; p++) p_s[tid + p*256] = e[p]*inv;
    __syncthreads();

    int d = tid & 63, g = tid >> 6;
    float acc = 0.f;
    for (int j = g*256; j < (g+1)*256; j++) acc += p_s[j] * Vp[(size_t)j*DH + d];
    red[tid] = acc; __syncthreads();
    if (g == 0) {
        float rsum = red[tid] + red[tid+64] + red[tid+128] + red[tid+192];
        int b_ = bh / HH, h_ = bh % HH;
        size_t idx = (size_t)(b_*SS)*EE + h_*DH + d;
        VALSh[idx] = __float2half(rsum);
    }
}

extern "C" void kernel_launch(void* const* d_in, const int* in_sizes, int n_in,
                              void* d_out, int out_size) {
    const float* x  = (const float*)d_in[0];
    const float* Wq = (const float*)d_in[1];
    const float* bq = (const float*)d_in[2];
    const float* Wk = (const float*)d_in[3];
    const float* bk = (const float*)d_in[4];
    const float* Wv = (const float*)d_in[5];
    const float* bv = (const float*)d_in[6];
    const float* Wo = (const float*)d_in[7];
    const float* bo = (const float*)d_in[8];
    const float* Wc = (const float*)d_in[9];
    const float* bc = (const float*)d_in[10];

    float* out  = (float*)d_out;
    float* attn = out + (size_t)BB*SS*EE;

    cudaFuncSetAttribute(proj_mm,    cudaFuncAttributeMaxDynamicSharedMemorySize, 61440);
    cudaFuncSetAttribute(out_mm,     cudaFuncAttributeMaxDynamicSharedMemorySize, 61440);
    cudaFuncSetAttribute(fused_attn, cudaFuncAttributeMaxDynamicSharedMemorySize, 143360);

    __half *xh, *wqh, *wql, *wkh, *wkl, *wvh, *wvl, *wch, *wcl, *woh, *wol;
    cudaGetSymbolAddress((void**)&xh, Xh);
    cudaGetSymbolAddress((void**)&wqh, WqHh); cudaGetSymbolAddress((void**)&wql, WqLh);
    cudaGetSymbolAddress((void**)&wkh, WkHh); cudaGetSymbolAddress((void**)&wkl, WkLh);
    cudaGetSymbolAddress((void**)&wvh, WvHh); cudaGetSymbolAddress((void**)&wvl, WvLh);
    cudaGetSymbolAddress((void**)&wch, WcHh); cudaGetSymbolAddress((void**)&wcl, WcLh);
    cudaGetSymbolAddress((void**)&woh, WoHh); cudaGetSymbolAddress((void**)&wol, WoLh);

    int nx4 = BB*SS*EE/4, nw4 = EE*EE/4;
    // 1: x -> fp16
    convXh_kernel<<<(nx4+255)/256, 256>>>(x, xh, nx4);
    // 2: Wq + Wk -> fp16 hi/lo x64
    convW2_kernel<<<dim3((nw4+255)/256, 2), 256>>>(Wq, wqh, wql, Wk, wkh, wkl, nw4);
    // 3: Wv + Wc
    convW2_kernel<<<dim3((nw4+255)/256, 2), 256>>>(Wv, wvh, wvl, Wc, wch, wcl, nw4);
    // 4: proj (ncu capture target)
    proj_mm<<<dim3(8,32,4), 256, 61440>>>(bq, bk, bv, bc);
    // 5: Wo
    convW_kernel<<<(nw4+255)/256, 256>>>(Wo, woh, wol, nw4);
    // 6-7: cls projection + q stats
    clsproj_kernel<<<BH, 64>>>(x, Wq, bq);
    qstats_kernel<<<BH*SQ/8, 256>>>();
    // 8: fused attention (incl. in-kernel attn normalization)
    fused_attn<<<dim3(8,BH), 256, 143360>>>(attn);
    // 9: cls output row
    cls_kernel<<<BH, 256>>>();
    // 10: output projection
    out_mm<<<dim3(8,33), 256, 61440>>>(bo, out);
}

// round 13
// speedup vs baseline: 1.1856x; 1.1856x over previous
#include <cuda_runtime.h>
#include <cuda_bf16.h>
#include <cuda_fp16.h>
#include <cstdint>

#define BB 4
#define SS 1025
#define SQ 1024
#define EE 1024
#define HH 16
#define DH 64
#define BH (BB*HH)
#define EPSF 1e-5f
#define MROWS_OUT (BB*SS)     // 4100
#define MTILES_OUT 33         // 33*128 = 4224

typedef __nv_bfloat16 bf16;

// ---------------- device scratch (allocation-free) ----------------
// NOTE: after fused_attn, QN2[row] holds the final row max (M) and
// QS[row] holds 1/rowsum (S) for attn_fix. Both arrays are dead for their
// original purpose by then (qstats consumed QS; each fused_attn block reads
// only its own QN2 rows at entry before overwriting them at exit).
__device__ float QS[BH*SQ*DH];          // fp32 q (qstats) -> later: 1/rowsum per row
__device__ float KS[BH*SQ*DH];          // fp32 k  (cls path)
__device__ float VS[BH*SQ*DH];          // fp32 v  (cls path)
__device__ __half Xh[BB*SS*EE];                       // x single fp16
__device__ __half WqHh[EE*EE], WqLh[EE*EE];           // 64*W fp16 hi/lo
__device__ __half WkHh[EE*EE], WkLh[EE*EE];
__device__ __half WvHh[EE*EE], WvLh[EE*EE];
__device__ __half WcHh[EE*EE], WcLh[EE*EE];
__device__ __half WoHh[EE*EE], WoLh[EE*EE];
__device__ __half Qh[BH*SQ*DH];                       // q single fp16
__device__ __half Khh[BH*SQ*DH], Klh[BH*SQ*DH];       // k fp16 hi/lo
__device__ __half VTHh[BH*DH*SQ], VTLh[BH*DH*SQ];     // (16*V)^T hi/lo
__device__ __half CPTHh[BH*DH*SQ], CPTLh[BH*DH*SQ];   // (16*CP)^T hi/lo
__device__ __half VALSh[(size_t)MTILES_OUT*128*EE];   // values, single fp16
__device__ float CVEC[BH*DH];
__device__ float CN2[BH];
__device__ float QN2[BH*SQ];            // |q|^2 -> later: row max per row
__device__ float CQg[BH*SQ];

// ---------------- warp-mma helpers ----------------
__device__ __forceinline__ uint32_t s2u(const void* p) {
    uint32_t a;
    asm("{ .reg .u64 t; cvta.to.shared.u64 t, %1; cvt.u32.u64 %0, t; }" : "=r"(a) : "l"(p));
    return a;
}
#define LDSM4(R0,R1,R2,R3,addr) \
    asm volatile("ldmatrix.sync.aligned.m8n8.x4.shared.b16 {%0,%1,%2,%3}, [%4];" \
        : "=r"(R0),"=r"(R1),"=r"(R2),"=r"(R3) : "r"(addr))

__device__ __forceinline__ void mma16816h(float* c, uint32_t a0, uint32_t a1,
                                          uint32_t a2, uint32_t a3,
                                          uint32_t b0, uint32_t b1) {
    asm volatile(
        "mma.sync.aligned.m16n8k16.row.col.f32.f16.f16.f32 "
        "{%0,%1,%2,%3}, {%4,%5,%6,%7}, {%8,%9}, {%0,%1,%2,%3};"
        : "+f"(c[0]), "+f"(c[1]), "+f"(c[2]), "+f"(c[3])
        : "r"(a0), "r"(a1), "r"(a2), "r"(a3), "r"(b0), "r"(b1));
}

// fp16 2-pass k16 step: A single, B hi/lo. MT*16 x 32 warp tile, pass-ordered.
template<int MT>
__device__ __forceinline__ void wmma_step2h(float (*acc)[4][4],
    uint32_t aB, uint32_t bHb, uint32_t bLb,
    int mrow0, int ncol0, int k0, int lane)
{
    uint32_t aF[MT][4];
    #pragma unroll
    for (int mi = 0; mi < MT; mi++) {
        uint32_t off = ((uint32_t)(mrow0 + mi*16 + (lane & 15))*40u + (uint32_t)k0 + ((lane >> 4) << 3)) * 2u;
        LDSM4(aF[mi][0], aF[mi][1], aF[mi][2], aF[mi][3], aB + off);
    }
    uint32_t bHf[4][2], bLf[4][2];
    int j = lane >> 3;
    #pragma unroll
    for (int p = 0; p < 2; p++) {
        uint32_t off = ((uint32_t)(ncol0 + p*16 + ((j >> 1) << 3) + (lane & 7))*40u + (uint32_t)k0 + ((j & 1) << 3)) * 2u;
        uint32_t r0, r1, r2, r3;
        LDSM4(r0, r1, r2, r3, bHb + off);
        bHf[p*2][0] = r0; bHf[p*2][1] = r1; bHf[p*2+1][0] = r2; bHf[p*2+1][1] = r3;
        LDSM4(r0, r1, r2, r3, bLb + off);
        bLf[p*2][0] = r0; bLf[p*2][1] = r1; bLf[p*2+1][0] = r2; bLf[p*2+1][1] = r3;
    }
    #pragma unroll
    for (int mi = 0; mi < MT; mi++)
        #pragma unroll
        for (int nj = 0; nj < 4; nj++)
            mma16816h(acc[mi][nj], aF[mi][0], aF[mi][1], aF[mi][2], aF[mi][3], bHf[nj][0], bHf[nj][1]);
    #pragma unroll
    for (int mi = 0; mi < MT; mi++)
        #pragma unroll
        for (int nj = 0; nj < 4; nj++)
            mma16816h(acc[mi][nj], aF[mi][0], aF[mi][1], aF[mi][2], aF[mi][3], bLf[nj][0], bLf[nj][1]);
}

// 4 n8-frags (32 cols) from smem tile (stride 40)
__device__ __forceinline__ void ldB32(uint32_t (*bf)[2], uint32_t base, int n0_, int k0, int lane) {
    int j = lane >> 3;
    #pragma unroll
    for (int p = 0; p < 2; p++) {
        uint32_t off = ((uint32_t)(n0_ + p*16 + ((j >> 1) << 3) + (lane & 7))*40u + (uint32_t)k0 + ((j & 1) << 3)) * 2u;
        uint32_t r0, r1, r2, r3;
        LDSM4(r0, r1, r2, r3, base + off);
        bf[p*2][0] = r0; bf[p*2][1] = r1; bf[p*2+1][0] = r2; bf[p*2+1][1] = r3;
    }
}

// load nrows x 32 b16 elems into smem tile (stride 40 elems) via cp.async
__device__ __forceinline__ void ld_tile32(uint32_t sdst, const void* gv, size_t rstride, int nrows) {
    const __half* g = (const __half*)gv;
    int tid = threadIdx.x;
    int tot = nrows * 4;
    for (int u = tid; u < tot; u += 256) {
        int r = u >> 2, c = u & 3;
        uint32_t dst = sdst + (uint32_t)(r*80 + c*16);
        const __half* src = g + (size_t)r * rstride + (c << 3);
        asm volatile("cp.async.cg.shared.global [%0], [%1], 16;" :: "r"(dst), "l"(src) : "memory");
    }
}
#define CPA_COMMIT() asm volatile("cp.async.commit_group;" ::: "memory")
#define CPA_WAIT1()  asm volatile("cp.async.wait_group 1;" ::: "memory")
#define CPA_WAIT0()  asm volatile("cp.async.wait_group 0;" ::: "memory")

__device__ __forceinline__ void split2h(float v, __half& h, __half& l) {
    h = __float2half(v);
    l = __float2half(v - __half2float(h));
}
__device__ __forceinline__ uint32_t packh2(float a, float b) {
    __half2 t = __floats2half2_rn(a, b);
    return *(uint32_t*)&t;
}
__device__ __forceinline__ uint32_t packh2x(__half a, __half b) {
    return (uint32_t)__half_as_ushort(a) | ((uint32_t)__half_as_ushort(b) << 16);
}

// ============================================================
// conversions
// ============================================================
__global__ void convXh_kernel(const float* __restrict__ s, __half* __restrict__ h, int n4) {
    int i = blockIdx.x * 256 + threadIdx.x;
    if (i >= n4) return;
    float4 v = ((const float4*)s)[i];
    uint2 hp;
    hp.x = packh2(v.x, v.y); hp.y = packh2(v.z, v.w);
    ((uint2*)h)[i] = hp;
}
__device__ __forceinline__ void convW_body(const float* __restrict__ s,
                                           __half* __restrict__ h,
                                           __half* __restrict__ l, int i) {
    float4 v = ((const float4*)s)[i];
    __half h0, h1, h2, h3, l0, l1, l2, l3;
    split2h(v.x*64.f, h0, l0); split2h(v.y*64.f, h1, l1);
    split2h(v.z*64.f, h2, l2); split2h(v.w*64.f, h3, l3);
    uint2 hp, lp;
    hp.x = packh2x(h0, h1); hp.y = packh2x(h2, h3);
    lp.x = packh2x(l0, l1); lp.y = packh2x(l2, l3);
    ((uint2*)h)[i] = hp;
    ((uint2*)l)[i] = lp;
}
__global__ void convW_kernel(const float* __restrict__ s, __half* __restrict__ h,
                             __half* __restrict__ l, int n4) {
    int i = blockIdx.x * 256 + threadIdx.x;
    if (i >= n4) return;
    convW_body(s, h, l, i);
}
__global__ void convW2_kernel(const float* __restrict__ s0, __half* __restrict__ h0,
                              __half* __restrict__ l0,
                              const float* __restrict__ s1, __half* __restrict__ h1,
                              __half* __restrict__ l1, int n4) {
    int i = blockIdx.x * 256 + threadIdx.x;
    if (i >= n4) return;
    if (blockIdx.y == 0) convW_body(s0, h0, l0, i);
    else                 convW_body(s1, h1, l1, i);
}

// ============================================================
// proj: 128x128 tile of (x @ (64W)^T)/64 + b. fp16 2-pass. grid(8,32,4)
// ============================================================
__global__ void __launch_bounds__(256) proj_mm(
    const float* __restrict__ b0, const float* __restrict__ b1,
    const float* __restrict__ b2, const float* __restrict__ b3)
{
    extern __shared__ uint8_t dyn[];
    uint32_t sb = s2u(dyn);
    int tid = threadIdx.x, wid = tid >> 5, lane = tid & 31;

    int w = blockIdx.z;
    const __half* WHp = (w==0)?WqHh:(w==1)?WkHh:(w==2)?WvHh:WcHh;
    const __half* WLp = (w==0)?WqLh:(w==1)?WkLh:(w==2)?WvLh:WcLh;
    const float* bias = (w==0)?b0:(w==1)?b1:(w==2)?b2:b3;

    int m0 = blockIdx.y * 128, n0 = blockIdx.x * 128;
    int b_ = m0 >> 10, i0 = m0 & 1023;

    const __half* aF = Xh + (size_t)(b_*SS + i0 + 1)*EE;
    const __half* bH = WHp + (size_t)n0*EE;
    const __half* bL = WLp + (size_t)n0*EE;

    float acc[4][4][4] = {};
    int wm = wid & 1, wn = wid >> 1;
    int mrow0 = wm*64, ncol0 = wn*32;

    ld_tile32(sb,         aF, EE, 128);
    ld_tile32(sb + 10240, bH, EE, 128);
    ld_tile32(sb + 20480, bL, EE, 128);
    CPA_COMMIT();
    int buf = 0;
    for (int ch = 0; ch < 32; ch++) {
        if (ch + 1 < 32) {
            uint32_t nb = sb + (buf^1)*30720;
            int kt = (ch + 1) * 32;
            ld_tile32(nb,         aF + kt, EE, 128);
            ld_tile32(nb + 10240, bH + kt, EE, 128);
            ld_tile32(nb + 20480, bL + kt, EE, 128);
            CPA_COMMIT();
            CPA_WAIT1();
        } else CPA_WAIT0();
        __syncthreads();
        uint32_t base = sb + buf*30720;
        wmma_step2h<4>(acc, base, base+10240, base+20480, mrow0, ncol0, 0,  lane);
        wmma_step2h<4>(acc, base, base+10240, base+20480, mrow0, ncol0, 16, lane);
        __syncthreads();
        buf ^= 1;
    }

    int rbase = mrow0 + (lane >> 2);
    int cbase = ncol0 + (lane & 3)*2;
    const float inv64 = 1.0f/64.0f;
    #pragma unroll
    for (int mi = 0; mi < 4; mi++)
        #pragma unroll
        for (int half = 0; half < 2; half++) {
            int i = i0 + rbase + mi*16 + half*8;
            #pragma unroll
            for (int nj = 0; nj < 4; nj++) {
                int col = n0 + cbase + nj*8;
                int h2 = col >> 6, d2 = col & 63;
                float v0 = acc[mi][nj][half*2]*inv64   + bias[col];
                float v1 = acc[mi][nj][half*2+1]*inv64 + bias[col+1];
                size_t qi = ((size_t)(b_*HH + h2)*SQ + i)*DH + d2;
                size_t ti = ((size_t)(b_*HH + h2)*DH + d2)*SQ + i;
                if (w == 0) {
                    *(float2*)&QS[qi] = make_float2(v0, v1);
                    *(uint32_t*)&Qh[qi] = packh2(v0, v1);
                } else if (w == 1) {
                    *(float2*)&KS[qi] = make_float2(v0, v1);
                    __half h0v, l0v, h1v, l1v;
                    split2h(v0, h0v, l0v); split2h(v1, h1v, l1v);
                    *(uint32_t*)&Khh[qi] = packh2x(h0v, h1v);
                    *(uint32_t*)&Klh[qi] = packh2x(l0v, l1v);
                } else if (w == 2) {
                    *(float2*)&VS[qi] = make_float2(v0, v1);
                    __half h0v, l0v, h1v, l1v;
                    split2h(v0*16.f, h0v, l0v); split2h(v1*16.f, h1v, l1v);
                    VTHh[ti] = h0v;      VTLh[ti] = l0v;
                    VTHh[ti + SQ] = h1v; VTLh[ti + SQ] = l1v;
                } else {
                    __half h0v, l0v, h1v, l1v;
                    split2h(v0*16.f, h0v, l0v); split2h(v1*16.f, h1v, l1v);
                    CPTHh[ti] = h0v;      CPTLh[ti] = l0v;
                    CPTHh[ti + SQ] = h1v; CPTLh[ti + SQ] = l1v;
                }
            }
        }
}

// ============================================================
// fused attention: S = Qh·K(hi/lo) fp16 2-pass -> raw l to attn,
// dual online softmax, O1 += P1@V, O2 += P2@CP (fp16 2-pass).
// grid(8,64) block 256. smem: Q 20480 + 2 x 61440 = 143360
// ============================================================
__global__ void __launch_bounds__(256) fused_attn(float* __restrict__ attn)
{
    extern __shared__ uint8_t dyn[];
    uint32_t sQ = s2u(dyn);
    uint32_t sT = sQ + 20480;
    int tid = threadIdx.x, wid = tid >> 5, lane = tid & 31;
    int bh = blockIdx.y;
    int m0 = blockIdx.x * 128;
    int mrow0 = wid * 16;
    int g = lane >> 2, tig = lane & 3;
    int r0 = mrow0 + g, r1 = r0 + 8;
    int gr0 = m0 + r0, gr1 = m0 + r1;

    float qn0 = QN2[(size_t)bh*SQ + gr0], qn1 = QN2[(size_t)bh*SQ + gr1];
    float cn = CN2[bh];
    float sc0 = rsqrtf(64.0f * qn0), sc1r = rsqrtf(64.0f * qn1);
    float rr0 = rsqrtf(qn0 * cn), rr1 = rsqrtf(qn1 * cn);

    float* attnb = attn + (size_t)bh*SQ*SQ;
    const float* cqrow = CQg + (size_t)bh*SQ;

    {
        const __half* qh = Qh + (size_t)bh*SQ*DH + (size_t)m0*DH;
        ld_tile32(sQ,         qh,      DH, 128);
        ld_tile32(sQ + 10240, qh + 32, DH, 128);
        CPA_COMMIT();
    }

    #define FLOAD(bb, jt) do { \
        int j0_ = (jt) * 64; \
        const __half* kh_ = Khh + (size_t)bh*SQ*DH + (size_t)j0_*DH; \
        const __half* kl_ = Klh + (size_t)bh*SQ*DH + (size_t)j0_*DH; \
        const __half* vh_ = VTHh + (size_t)bh*DH*SQ + j0_; \
        const __half* vl_ = VTLh + (size_t)bh*DH*SQ + j0_; \
        const __half* ph_ = CPTHh + (size_t)bh*DH*SQ + j0_; \
        const __half* pl_ = CPTLh + (size_t)bh*DH*SQ + j0_; \
        ld_tile32((bb),        kh_,      DH, 64); \
        ld_tile32((bb)+5120,   kh_ + 32, DH, 64); \
        ld_tile32((bb)+10240,  kl_,      DH, 64); \
        ld_tile32((bb)+15360,  kl_ + 32, DH, 64); \
        ld_tile32((bb)+20480,  vh_,      SQ, 64); \
        ld_tile32((bb)+25600,  vh_ + 32, SQ, 64); \
        ld_tile32((bb)+30720,  vl_,      SQ, 64); \
        ld_tile32((bb)+35840,  vl_ + 32, SQ, 64); \
        ld_tile32((bb)+40960,  ph_,      SQ, 64); \
        ld_tile32((bb)+46080,  ph_ + 32, SQ, 64); \
        ld_tile32((bb)+51200,  pl_,      SQ, 64); \
        ld_tile32((bb)+56320,  pl_ + 32, SQ, 64); \
        CPA_COMMIT(); \
    } while (0)

    float O1[8][4] = {}, O2[8][4] = {};
    float m1_0 = -1e30f, m1_1 = -1e30f, m2_0 = -1e30f, m2_1 = -1e30f;
    float s1_0 = 0.f, s1_1 = 0.f, s2_0 = 0.f, s2_1 = 0.f;

    FLOAD(sT, 0);
    int buf = 0;
    for (int jt = 0; jt < 16; jt++) {
        if (jt + 1 < 16) { FLOAD(sT + (buf^1)*61440, jt + 1); CPA_WAIT1(); }
        else CPA_WAIT0();
        __syncthreads();
        uint32_t bb = sT + buf*61440;
        int j0 = jt * 64;

        // ---- S = Qh · K (fp16 2-pass) ----
        float S[8][4] = {};
        #pragma unroll
        for (int kk = 0; kk < 64; kk += 16) {
            int cch = kk >> 5, k0 = kk & 16;
            uint32_t aQ = sQ + cch*10240;
            uint32_t a0, a1, a2, a3;
            uint32_t offA = ((uint32_t)(mrow0 + (lane & 15))*40u + (uint32_t)k0 + ((lane >> 4) << 3)) * 2u;
            LDSM4(a0, a1, a2, a3, aQ + offA);
            uint32_t bHf[4][2], bLf[4][2], bHf2[4][2], bLf2[4][2];
            uint32_t kbH = bb + cch*5120, kbL = bb + 10240 + cch*5120;
            ldB32(bHf,  kbH, 0,  k0, lane);
            ldB32(bHf2, kbH, 32, k0, lane);
            ldB32(bLf,  kbL, 0,  k0, lane);
            ldB32(bLf2, kbL, 32, k0, lane);
            #pragma unroll
            for (int f = 0; f < 4; f++) {
                mma16816h(S[f],   a0, a1, a2, a3, bHf[f][0],  bHf[f][1]);
                mma16816h(S[f+4], a0, a1, a2, a3, bHf2[f][0], bHf2[f][1]);
            }
            #pragma unroll
            for (int f = 0; f < 4; f++) {
                mma16816h(S[f],   a0, a1, a2, a3, bLf[f][0],  bLf[f][1]);
                mma16816h(S[f+4], a0, a1, a2, a3, bLf2[f][0], bLf2[f][1]);
            }
        }

        // ---- scale to l, store raw, track maxes ----
        float cqv[8][2];
        float lmax0 = -1e30f, lmax1 = -1e30f, l2max0 = -1e30f, l2max1 = -1e30f;
        #pragma unroll
        for (int f = 0; f < 8; f++) {
            int col = j0 + f*8 + tig*2;
            float2 cq = *(const float2*)&cqrow[col];
            cqv[f][0] = cq.x; cqv[f][1] = cq.y;
            S[f][0] *= sc0;  S[f][1] *= sc0;
            S[f][2] *= sc1r; S[f][3] *= sc1r;
            *(float2*)&attnb[(size_t)gr0*SQ + col] = make_float2(S[f][0], S[f][1]);
            *(float2*)&attnb[(size_t)gr1*SQ + col] = make_float2(S[f][2], S[f][3]);
            lmax0 = fmaxf(lmax0, fmaxf(S[f][0], S[f][1]));
            lmax1 = fmaxf(lmax1, fmaxf(S[f][2], S[f][3]));
            l2max0 = fmaxf(l2max0, fmaxf(S[f][0]*cq.x*rr0, S[f][1]*cq.y*rr0));
            l2max1 = fmaxf(l2max1, fmaxf(S[f][2]*cq.x*rr1, S[f][3]*cq.y*rr1));
        }
        #pragma unroll
        for (int o = 1; o <= 2; o <<= 1) {
            lmax0  = fmaxf(lmax0,  __shfl_xor_sync(0xffffffffu, lmax0,  o));
            lmax1  = fmaxf(lmax1,  __shfl_xor_sync(0xffffffffu, lmax1,  o));
            l2max0 = fmaxf(l2max0, __shfl_xor_sync(0xffffffffu, l2max0, o));
            l2max1 = fmaxf(l2max1, __shfl_xor_sync(0xffffffffu, l2max1, o));
        }
        float m1n0 = fmaxf(m1_0, lmax0),  m1n1 = fmaxf(m1_1, lmax1);
        float m2n0 = fmaxf(m2_0, l2max0), m2n1 = fmaxf(m2_1, l2max1);
        float f10 = __expf(m1_0 - m1n0), f11 = __expf(m1_1 - m1n1);
        float f20 = __expf(m2_0 - m2n0), f21 = __expf(m2_1 - m2n1);
        m1_0 = m1n0; m1_1 = m1n1; m2_0 = m2n0; m2_1 = m2n1;
        #pragma unroll
        for (int f = 0; f < 8; f++) {
            O1[f][0] *= f10; O1[f][1] *= f10; O1[f][2] *= f11; O1[f][3] *= f11;
            O2[f][0] *= f20; O2[f][1] *= f20; O2[f][2] *= f21; O2[f][3] *= f21;
        }

        // ---- path 1: O1 += P1 @ (16V), fp16 2-pass ----
        {
            uint32_t ph01[8], ph23[8];
            float ps0 = 0.f, ps1 = 0.f;
            #pragma unroll
            for (int f = 0; f < 8; f++) {
                float p0 = __expf(S[f][0] - m1n0), p1v = __expf(S[f][1] - m1n0);
                float p2v = __expf(S[f][2] - m1n1), p3v = __expf(S[f][3] - m1n1);
                ps0 += p0 + p1v; ps1 += p2v + p3v;
                ph01[f] = packh2(p0, p1v);
                ph23[f] = packh2(p2v, p3v);
            }
            #pragma unroll
            for (int o = 1; o <= 2; o <<= 1) {
                ps0 += __shfl_xor_sync(0xffffffffu, ps0, o);
                ps1 += __shfl_xor_sync(0xffffffffu, ps1, o);
            }
            s1_0 = s1_0 * f10 + ps0; s1_1 = s1_1 * f11 + ps1;
            #pragma unroll
            for (int kk = 0; kk < 64; kk += 16) {
                int cch = kk >> 5, k0 = kk & 16;
                int gp = kk >> 3;
                uint32_t vbH = bb + 20480 + cch*5120, vbL = bb + 30720 + cch*5120;
                uint32_t bHf[4][2], bLf[4][2], bHf2[4][2], bLf2[4][2];
                ldB32(bHf,  vbH, 0,  k0, lane);
                ldB32(bHf2, vbH, 32, k0, lane);
                ldB32(bLf,  vbL, 0,  k0, lane);
                ldB32(bLf2, vbL, 32, k0, lane);
                uint32_t a0 = ph01[gp], a1 = ph23[gp], a2 = ph01[gp+1], a3 = ph23[gp+1];
                #pragma unroll
                for (int f = 0; f < 4; f++) {
                    mma16816h(O1[f],   a0, a1, a2, a3, bHf[f][0],  bHf[f][1]);
                    mma16816h(O1[f+4], a0, a1, a2, a3, bHf2[f][0], bHf2[f][1]);
                }
                #pragma unroll
                for (int f = 0; f < 4; f++) {
                    mma16816h(O1[f],   a0, a1, a2, a3, bLf[f][0],  bLf[f][1]);
                    mma16816h(O1[f+4], a0, a1, a2, a3, bLf2[f][0], bLf2[f][1]);
                }
            }
        }

        // ---- path 2: O2 += P2 @ (16CP), fp16 2-pass ----
        {
            uint32_t ph01[8], ph23[8];
            float ps0 = 0.f, ps1 = 0.f;
            #pragma unroll
            for (int f = 0; f < 8; f++) {
                float p0 = __expf(S[f][0]*cqv[f][0]*rr0 - m2n0);
                float p1v = __expf(S[f][1]*cqv[f][1]*rr0 - m2n0);
                float p2v = __expf(S[f][2]*cqv[f][0]*rr1 - m2n1);
                float p3v = __expf(S[f][3]*cqv[f][1]*rr1 - m2n1);
                ps0 += p0 + p1v; ps1 += p2v + p3v;
                ph01[f] = packh2(p0, p1v);
                ph23[f] = packh2(p2v, p3v);
            }
            #pragma unroll
            for (int o = 1; o <= 2; o <<= 1) {
                ps0 += __shfl_xor_sync(0xffffffffu, ps0, o);
                ps1 += __shfl_xor_sync(0xffffffffu, ps1, o);
            }
            s2_0 = s2_0 * f20 + ps0; s2_1 = s2_1 * f21 + ps1;
            #pragma unroll
            for (int kk = 0; kk < 64; kk += 16) {
                int cch = kk >> 5, k0 = kk & 16;
                int gp = kk >> 3;
                uint32_t pbH = bb + 40960 + cch*5120, pbL = bb + 51200 + cch*5120;
                uint32_t bHf[4][2], bLf[4][2], bHf2[4][2], bLf2[4][2];
                ldB32(bHf,  pbH, 0,  k0, lane);
                ldB32(bHf2, pbH, 32, k0, lane);
                ldB32(bLf,  pbL, 0,  k0, lane);
                ldB32(bLf2, pbL, 32, k0, lane);
                uint32_t a0 = ph01[gp], a1 = ph23[gp], a2 = ph01[gp+1], a3 = ph23[gp+1];
                #pragma unroll
                for (int f = 0; f < 4; f++) {
                    mma16816h(O2[f],   a0, a1, a2, a3, bHf[f][0],  bHf[f][1]);
                    mma16816h(O2[f+4], a0, a1, a2, a3, bHf2[f][0], bHf2[f][1]);
                }
                #pragma unroll
                for (int f = 0; f < 4; f++) {
                    mma16816h(O2[f],   a0, a1, a2, a3, bLf[f][0],  bLf[f][1]);
                    mma16816h(O2[f+4], a0, a1, a2, a3, bLf2[f][0], bLf2[f][1]);
                }
            }
        }
        __syncthreads();
        buf ^= 1;
    }
    #undef FLOAD

    // ---- epilogue: values rows (/16 undoes V/CP scale) + stats ----
    int b_ = bh / HH, h_ = bh % HH;
    float is10 = 0.0625f/s1_0, is11 = 0.0625f/s1_1, is20 = 0.0625f/s2_0, is21 = 0.0625f/s2_1;
    size_t ob0 = (size_t)(b_*SS + 1 + gr0)*EE + h_*DH;
    size_t ob1 = (size_t)(b_*SS + 1 + gr1)*EE + h_*DH;
    #pragma unroll
    for (int f = 0; f < 8; f++) {
        int d = f*8 + tig*2;
        float v0 = O1[f][0]*is10 + O2[f][0]*is20;
        float v1 = O1[f][1]*is10 + O2[f][1]*is20;
        float v2 = O1[f][2]*is11 + O2[f][2]*is21;
        float v3 = O1[f][3]*is11 + O2[f][3]*is21;
        *(uint32_t*)&VALSh[ob0 + d] = packh2(v0, v1);
        *(uint32_t*)&VALSh[ob1 + d] = packh2(v2, v3);
    }
    // stats into dead scratch: QN2[row] <- row max, QS[row] <- 1/rowsum.
    // (This block is the sole reader/writer of its QN2 rows; QS is dead.)
    if (tig == 0) {
        QN2[(size_t)bh*SQ + gr0] = m1_0; QS[(size_t)bh*SQ + gr0] = 1.f/s1_0;
        QN2[(size_t)bh*SQ + gr1] = m1_1; QS[(size_t)bh*SQ + gr1] = 1.f/s1_1;
    }
}

// ============================================================
// attn_fix: attn = exp(l - M)/S in place. one row per block.
// M from QN2, 1/S from QS (stashed by fused_attn).
// ============================================================
__global__ void attn_fix(float* __restrict__ attn) {
    int row = blockIdx.x;
    float m = QN2[row], si = QS[row];
    float4* p = (float4*)(attn + (size_t)row*SQ);
    float4 v = p[threadIdx.x];
    v.x = __expf(v.x - m)*si;
    v.y = __expf(v.y - m)*si;
    v.z = __expf(v.z - m)*si;
    v.w = __expf(v.w - m)*si;
    p[threadIdx.x] = v;
}

// ============================================================
// out: VALS(f16) @ (64Wo)^T/64 + bo. fp16 2-pass. grid(8,33)
// ============================================================
__global__ void __launch_bounds__(256) out_mm(const float* __restrict__ bo,
                                             float* __restrict__ out)
{
    extern __shared__ uint8_t dyn[];
    uint32_t sb = s2u(dyn);
    int tid = threadIdx.x, wid = tid >> 5, lane = tid & 31;
    int m0 = blockIdx.y * 128, n0 = blockIdx.x * 128;

    const __half* aF = VALSh + (size_t)m0*EE;
    const __half* bH = WoHh + (size_t)n0*EE;
    const __half* bL = WoLh + (size_t)n0*EE;

    float acc[4][4][4] = {};
    int wm = wid & 1, wn = wid >> 1;
    int mrow0 = wm*64, ncol0 = wn*32;

    ld_tile32(sb,         aF, EE, 128);
    ld_tile32(sb + 10240, bH, EE, 128);
    ld_tile32(sb + 20480, bL, EE, 128);
    CPA_COMMIT();
    int buf = 0;
    for (int ch = 0; ch < 32; ch++) {
        if (ch + 1 < 32) {
            uint32_t nb = sb + (buf^1)*30720;
            int kt = (ch + 1) * 32;
            ld_tile32(nb,         aF + kt, EE, 128);
            ld_tile32(nb + 10240, bH + kt, EE, 128);
            ld_tile32(nb + 20480, bL + kt, EE, 128);
            CPA_COMMIT();
            CPA_WAIT1();
        } else CPA_WAIT0();
        __syncthreads();
        uint32_t base = sb + buf*30720;
        wmma_step2h<4>(acc, base, base+10240, base+20480, mrow0, ncol0, 0,  lane);
        wmma_step2h<4>(acc, base, base+10240, base+20480, mrow0, ncol0, 16, lane);
        __syncthreads();
        buf ^= 1;
    }

    int rbase = mrow0 + (lane >> 2);
    int cbase = ncol0 + (lane & 3)*2;
    const float inv64 = 1.0f/64.0f;
    #pragma unroll
    for (int mi = 0; mi < 4; mi++)
        #pragma unroll
        for (int half = 0; half < 2; half++) {
            int mr = m0 + rbase + mi*16 + half*8;
            if (mr >= MROWS_OUT) continue;
            #pragma unroll
            for (int nj = 0; nj < 4; nj++) {
                int col = n0 + cbase + nj*8;
                *(float2*)&out[(size_t)mr*EE + col] =
                    make_float2(acc[mi][nj][half*2]*inv64 + bo[col],
                                acc[mi][nj][half*2+1]*inv64 + bo[col+1]);
            }
        }
}

// ============================================================
// cls token projection + CN2. grid BH, block 64
// ============================================================
__global__ void clsproj_kernel(const float* __restrict__ x,
                               const float* __restrict__ Wq,
                               const float* __restrict__ bq) {
    int bh = blockIdx.x;
    int b_ = bh / HH, h_ = bh % HH;
    int d  = threadIdx.x;
    int j  = h_*DH + d;
    const float* xr = x  + (size_t)(b_*SS)*EE;
    const float* wr = Wq + (size_t)j*EE;
    float s = 0.f;
    for (int e = 0; e < EE; e += 4) {
        float4 xv = *(const float4*)(xr + e);
        float4 wv = *(const float4*)(wr + e);
        s += xv.x*wv.x + xv.y*wv.y + xv.z*wv.z + xv.w*wv.w;
    }
    s += bq[j];
    CVEC[bh*DH + d] = s;
    __shared__ float red[64];
    red[d] = s*s; __syncthreads();
    for (int o = 32; o > 0; o >>= 1) { if (d < o) red[d] += red[d+o]; __syncthreads(); }
    if (d == 0) CN2[bh] = fmaxf(red[0], EPSF);
}

// ============================================================
// per-row q stats: QN2 and CQ. grid BH*SQ/8, block 256
// ============================================================
__global__ void qstats_kernel() {
    int row  = blockIdx.x*8 + (threadIdx.x >> 5);
    int lane = threadIdx.x & 31;
    int bh   = row >> 10;
    const float* qr = QS   + (size_t)row*DH;
    const float* cv = CVEC + bh*DH;
    float n2 = 0.f, cq = 0.f;
    #pragma unroll
    for (int d = lane; d < DH; d += 32) {
        float qv = qr[d];
        n2 += qv*qv;
        cq += qv*cv[d];
    }
    #pragma unroll
    for (int o = 16; o > 0; o >>= 1) {
        n2 += __shfl_xor_sync(0xffffffffu, n2, o);
        cq += __shfl_xor_sync(0xffffffffu, cq, o);
    }
    if (lane == 0) { QN2[row] = fmaxf(n2, EPSF); CQg[row] = cq; }
}

// ============================================================
// cls path: ck softmax -> cls_out row (fp16 into VALS). grid BH, block 256
// ============================================================
__global__ void cls_kernel() {
    int bh = blockIdx.x;
    int tid = threadIdx.x;
    const float* Kp = KS + (size_t)bh*SQ*DH;
    const float* Vp = VS + (size_t)bh*SQ*DH;
    __shared__ float p_s[SQ];
    __shared__ float red[256];
    __shared__ float c_s[DH];
    if (tid < DH) c_s[tid] = CVEC[bh*DH + tid];
    __syncthreads();

    float scale = rsqrtf(64.0f * CN2[bh]);
    float lo[4];
    #pragma unroll
    for (int p = 0; p < 4; p++) {
        int j = tid + p*256;
        const float* kr = Kp + (size_t)j*DH;
        float s = 0.f;
        #pragma unroll
        for (int d = 0; d < DH; d += 4) {
            float4 kv = *(const float4*)(kr + d);
            s += c_s[d]*kv.x + c_s[d+1]*kv.y + c_s[d+2]*kv.z + c_s[d+3]*kv.w;
        }
        lo[p] = s * scale;
    }
    float m = fmaxf(fmaxf(lo[0],lo[1]), fmaxf(lo[2],lo[3]));
    red[tid] = m; __syncthreads();
    #pragma unroll
    for (int o = 128; o > 0; o >>= 1) { if (tid < o) red[tid] = fmaxf(red[tid], red[tid+o]); __syncthreads(); }
    m = red[0]; __syncthreads();
    float e[4], s = 0.f;
    #pragma unroll
    for (int p = 0; p < 4; p++) { e[p] = __expf(lo[p] - m); s += e[p]; }
    red[tid] = s; __syncthreads();
    #pragma unroll
    for (int o = 128; o > 0; o >>= 1) { if (tid < o) red[tid] += red[tid+o]; __syncthreads(); }
    float inv = 1.0f / red[0]; __syncthreads();
    #pragma unroll
    for (int p = 0; p < 4; p++) p_s[tid + p*256] = e[p]*inv;
    __syncthreads();

    int d = tid & 63, g = tid >> 6;
    float acc = 0.f;
    for (int j = g*256; j < (g+1)*256; j++) acc += p_s[j] * Vp[(size_t)j*DH + d];
    red[tid] = acc; __syncthreads();
    if (g == 0) {
        float rsum = red[tid] + red[tid+64] + red[tid+128] + red[tid+192];
        int b_ = bh / HH, h_ = bh % HH;
        size_t idx = (size_t)(b_*SS)*EE + h_*DH + d;
        VALSh[idx] = __float2half(rsum);
    }
}

extern "C" void kernel_launch(void* const* d_in, const int* in_sizes, int n_in,
                              void* d_out, int out_size) {
    const float* x  = (const float*)d_in[0];
    const float* Wq = (const float*)d_in[1];
    const float* bq = (const float*)d_in[2];
    const float* Wk = (const float*)d_in[3];
    const float* bk = (const float*)d_in[4];
    const float* Wv = (const float*)d_in[5];
    const float* bv = (const float*)d_in[6];
    const float* Wo = (const float*)d_in[7];
    const float* bo = (const float*)d_in[8];
    const float* Wc = (const float*)d_in[9];
    const float* bc = (const float*)d_in[10];

    float* out  = (float*)d_out;
    float* attn = out + (size_t)BB*SS*EE;

    cudaFuncSetAttribute(proj_mm,    cudaFuncAttributeMaxDynamicSharedMemorySize, 61440);
    cudaFuncSetAttribute(out_mm,     cudaFuncAttributeMaxDynamicSharedMemorySize, 61440);
    cudaFuncSetAttribute(fused_attn, cudaFuncAttributeMaxDynamicSharedMemorySize, 143360);

    __half *xh, *wqh, *wql, *wkh, *wkl, *wvh, *wvl, *wch, *wcl, *woh, *wol;
    cudaGetSymbolAddress((void**)&xh, Xh);
    cudaGetSymbolAddress((void**)&wqh, WqHh); cudaGetSymbolAddress((void**)&wql, WqLh);
    cudaGetSymbolAddress((void**)&wkh, WkHh); cudaGetSymbolAddress((void**)&wkl, WkLh);
    cudaGetSymbolAddress((void**)&wvh, WvHh); cudaGetSymbolAddress((void**)&wvl, WvLh);
    cudaGetSymbolAddress((void**)&wch, WcHh); cudaGetSymbolAddress((void**)&wcl, WcLh);
    cudaGetSymbolAddress((void**)&woh, WoHh); cudaGetSymbolAddress((void**)&wol, WoLh);

    int nx4 = BB*SS*EE/4, nw4 = EE*EE/4;
    // 1: x -> fp16
    convXh_kernel<<<(nx4+255)/256, 256>>>(x, xh, nx4);
    // 2: Wq + Wk -> fp16 hi/lo x64
    convW2_kernel<<<dim3((nw4+255)/256, 2), 256>>>(Wq, wqh, wql, Wk, wkh, wkl, nw4);
    // 3: Wv + Wc
    convW2_kernel<<<dim3((nw4+255)/256, 2), 256>>>(Wv, wvh, wvl, Wc, wch, wcl, nw4);
    // 4: proj (ncu capture target)
    proj_mm<<<dim3(8,32,4), 256, 61440>>>(bq, bk, bv, bc);
    // 5: Wo
    convW_kernel<<<(nw4+255)/256, 256>>>(Wo, woh, wol, nw4);
    // 6-7: cls projection + q stats
    clsproj_kernel<<<BH, 64>>>(x, Wq, bq);
    qstats_kernel<<<BH*SQ/8, 256>>>();
    // 8: fused attention (stats -> QN2/QS dead scratch)
    fused_attn<<<dim3(8,BH), 256, 143360>>>(attn);
    // 9: attn normalization (flat bandwidth-bound kernel)
    attn_fix<<<BH*SQ, 256>>>(attn);
    // 10: cls output row
    cls_kernel<<<BH, 256>>>();
    // 11: output projection
    out_mm<<<dim3(8,33), 256, 61440>>>(bo, out);
}

// round 14
// speedup vs baseline: 1.3243x; 1.1170x over previous
#include <cuda_runtime.h>
#include <cuda_bf16.h>
#include <cuda_fp16.h>
#include <cstdint>

#define BB 4
#define SS 1025
#define SQ 1024
#define EE 1024
#define HH 16
#define DH 64
#define BH (BB*HH)
#define EPSF 1e-5f
#define MROWS_OUT (BB*SS)     // 4100
#define MTILES_OUT 33         // 33*128 = 4224

typedef __nv_bfloat16 bf16;

// ---------------- device scratch (allocation-free) ----------------
// After fused_attn: QN2[row] = final row max (M), QS[row] = 1/rowsum (S)
// for attn_fix (both arrays dead for their original purpose by then).
__device__ float QS[BH*SQ*DH];          // fp32 q (qstats) -> later 1/rowsum
__device__ float KS[BH*SQ*DH];          // fp32 k  (cls path)
__device__ float VS[BH*SQ*DH];          // fp32 v  (cls path)
__device__ __half Xh[BB*SS*EE];                       // x single fp16
__device__ __half WqHh[EE*EE], WqLh[EE*EE];           // 64*W fp16 hi/lo
__device__ __half WkHh[EE*EE], WkLh[EE*EE];
__device__ __half WvHh[EE*EE], WvLh[EE*EE];
__device__ __half WcHh[EE*EE], WcLh[EE*EE];
__device__ __half WoHh[EE*EE], WoLh[EE*EE];
__device__ __half Qh[BH*SQ*DH];                       // q single fp16
__device__ __half Kh16[BH*SQ*DH];                     // k single fp16
__device__ __half VTh[BH*DH*SQ];                      // V^T single fp16
__device__ __half CPTh[BH*DH*SQ];                     // cls_proj^T single fp16
__device__ __half VALSh[(size_t)MTILES_OUT*128*EE];   // values, single fp16
__device__ float CVEC[BH*DH];
__device__ float CN2[BH];
__device__ float QN2[BH*SQ];            // |q|^2 -> later row max
__device__ float CQg[BH*SQ];

// ---------------- warp-mma helpers ----------------
__device__ __forceinline__ uint32_t s2u(const void* p) {
    uint32_t a;
    asm("{ .reg .u64 t; cvta.to.shared.u64 t, %1; cvt.u32.u64 %0, t; }" : "=r"(a) : "l"(p));
    return a;
}
#define LDSM4(R0,R1,R2,R3,addr) \
    asm volatile("ldmatrix.sync.aligned.m8n8.x4.shared.b16 {%0,%1,%2,%3}, [%4];" \
        : "=r"(R0),"=r"(R1),"=r"(R2),"=r"(R3) : "r"(addr))

__device__ __forceinline__ void mma16816h(float* c, uint32_t a0, uint32_t a1,
                                          uint32_t a2, uint32_t a3,
                                          uint32_t b0, uint32_t b1) {
    asm volatile(
        "mma.sync.aligned.m16n8k16.row.col.f32.f16.f16.f32 "
        "{%0,%1,%2,%3}, {%4,%5,%6,%7}, {%8,%9}, {%0,%1,%2,%3};"
        : "+f"(c[0]), "+f"(c[1]), "+f"(c[2]), "+f"(c[3])
        : "r"(a0), "r"(a1), "r"(a2), "r"(a3), "r"(b0), "r"(b1));
}

// fp16 2-pass k16 step: A single, B hi/lo. MT*16 x 32 warp tile, pass-ordered.
template<int MT>
__device__ __forceinline__ void wmma_step2h(float (*acc)[4][4],
    uint32_t aB, uint32_t bHb, uint32_t bLb,
    int mrow0, int ncol0, int k0, int lane)
{
    uint32_t aF[MT][4];
    #pragma unroll
    for (int mi = 0; mi < MT; mi++) {
        uint32_t off = ((uint32_t)(mrow0 + mi*16 + (lane & 15))*40u + (uint32_t)k0 + ((lane >> 4) << 3)) * 2u;
        LDSM4(aF[mi][0], aF[mi][1], aF[mi][2], aF[mi][3], aB + off);
    }
    uint32_t bHf[4][2], bLf[4][2];
    int j = lane >> 3;
    #pragma unroll
    for (int p = 0; p < 2; p++) {
        uint32_t off = ((uint32_t)(ncol0 + p*16 + ((j >> 1) << 3) + (lane & 7))*40u + (uint32_t)k0 + ((j & 1) << 3)) * 2u;
        uint32_t r0, r1, r2, r3;
        LDSM4(r0, r1, r2, r3, bHb + off);
        bHf[p*2][0] = r0; bHf[p*2][1] = r1; bHf[p*2+1][0] = r2; bHf[p*2+1][1] = r3;
        LDSM4(r0, r1, r2, r3, bLb + off);
        bLf[p*2][0] = r0; bLf[p*2][1] = r1; bLf[p*2+1][0] = r2; bLf[p*2+1][1] = r3;
    }
    #pragma unroll
    for (int mi = 0; mi < MT; mi++)
        #pragma unroll
        for (int nj = 0; nj < 4; nj++)
            mma16816h(acc[mi][nj], aF[mi][0], aF[mi][1], aF[mi][2], aF[mi][3], bHf[nj][0], bHf[nj][1]);
    #pragma unroll
    for (int mi = 0; mi < MT; mi++)
        #pragma unroll
        for (int nj = 0; nj < 4; nj++)
            mma16816h(acc[mi][nj], aF[mi][0], aF[mi][1], aF[mi][2], aF[mi][3], bLf[nj][0], bLf[nj][1]);
}

// 4 n8-frags (32 cols) from smem tile (stride 40)
__device__ __forceinline__ void ldB32(uint32_t (*bf)[2], uint32_t base, int n0_, int k0, int lane) {
    int j = lane >> 3;
    #pragma unroll
    for (int p = 0; p < 2; p++) {
        uint32_t off = ((uint32_t)(n0_ + p*16 + ((j >> 1) << 3) + (lane & 7))*40u + (uint32_t)k0 + ((j & 1) << 3)) * 2u;
        uint32_t r0, r1, r2, r3;
        LDSM4(r0, r1, r2, r3, base + off);
        bf[p*2][0] = r0; bf[p*2][1] = r1; bf[p*2+1][0] = r2; bf[p*2+1][1] = r3;
    }
}

// load nrows x 32 b16 elems into smem tile (stride 40 elems) via cp.async
__device__ __forceinline__ void ld_tile32(uint32_t sdst, const void* gv, size_t rstride, int nrows) {
    const __half* g = (const __half*)gv;
    int tid = threadIdx.x;
    int tot = nrows * 4;
    for (int u = tid; u < tot; u += 256) {
        int r = u >> 2, c = u & 3;
        uint32_t dst = sdst + (uint32_t)(r*80 + c*16);
        const __half* src = g + (size_t)r * rstride + (c << 3);
        asm volatile("cp.async.cg.shared.global [%0], [%1], 16;" :: "r"(dst), "l"(src) : "memory");
    }
}
#define CPA_COMMIT() asm volatile("cp.async.commit_group;" ::: "memory")
#define CPA_WAIT1()  asm volatile("cp.async.wait_group 1;" ::: "memory")
#define CPA_WAIT0()  asm volatile("cp.async.wait_group 0;" ::: "memory")

__device__ __forceinline__ void split2h(float v, __half& h, __half& l) {
    h = __float2half(v);
    l = __float2half(v - __half2float(h));
}
__device__ __forceinline__ uint32_t packh2(float a, float b) {
    __half2 t = __floats2half2_rn(a, b);
    return *(uint32_t*)&t;
}
__device__ __forceinline__ uint32_t packh2x(__half a, __half b) {
    return (uint32_t)__half_as_ushort(a) | ((uint32_t)__half_as_ushort(b) << 16);
}

// ============================================================
// conversions
// ============================================================
__global__ void convXh_kernel(const float* __restrict__ s, __half* __restrict__ h, int n4) {
    int i = blockIdx.x * 256 + threadIdx.x;
    if (i >= n4) return;
    float4 v = ((const float4*)s)[i];
    uint2 hp;
    hp.x = packh2(v.x, v.y); hp.y = packh2(v.z, v.w);
    ((uint2*)h)[i] = hp;
}
__device__ __forceinline__ void convW_body(const float* __restrict__ s,
                                           __half* __restrict__ h,
                                           __half* __restrict__ l, int i) {
    float4 v = ((const float4*)s)[i];
    __half h0, h1, h2, h3, l0, l1, l2, l3;
    split2h(v.x*64.f, h0, l0); split2h(v.y*64.f, h1, l1);
    split2h(v.z*64.f, h2, l2); split2h(v.w*64.f, h3, l3);
    uint2 hp, lp;
    hp.x = packh2x(h0, h1); hp.y = packh2x(h2, h3);
    lp.x = packh2x(l0, l1); lp.y = packh2x(l2, l3);
    ((uint2*)h)[i] = hp;
    ((uint2*)l)[i] = lp;
}
__global__ void convW_kernel(const float* __restrict__ s, __half* __restrict__ h,
                             __half* __restrict__ l, int n4) {
    int i = blockIdx.x * 256 + threadIdx.x;
    if (i >= n4) return;
    convW_body(s, h, l, i);
}
__global__ void convW2_kernel(const float* __restrict__ s0, __half* __restrict__ h0,
                              __half* __restrict__ l0,
                              const float* __restrict__ s1, __half* __restrict__ h1,
                              __half* __restrict__ l1, int n4) {
    int i = blockIdx.x * 256 + threadIdx.x;
    if (i >= n4) return;
    if (blockIdx.y == 0) convW_body(s0, h0, l0, i);
    else                 convW_body(s1, h1, l1, i);
}

// ============================================================
// proj: 128x128 tile of (x @ (64W)^T)/64 + b. fp16 2-pass. grid(8,32,4)
// ============================================================
__global__ void __launch_bounds__(256) proj_mm(
    const float* __restrict__ b0, const float* __restrict__ b1,
    const float* __restrict__ b2, const float* __restrict__ b3)
{
    extern __shared__ uint8_t dyn[];
    uint32_t sb = s2u(dyn);
    int tid = threadIdx.x, wid = tid >> 5, lane = tid & 31;

    int w = blockIdx.z;
    const __half* WHp = (w==0)?WqHh:(w==1)?WkHh:(w==2)?WvHh:WcHh;
    const __half* WLp = (w==0)?WqLh:(w==1)?WkLh:(w==2)?WvLh:WcLh;
    const float* bias = (w==0)?b0:(w==1)?b1:(w==2)?b2:b3;

    int m0 = blockIdx.y * 128, n0 = blockIdx.x * 128;
    int b_ = m0 >> 10, i0 = m0 & 1023;

    const __half* aF = Xh + (size_t)(b_*SS + i0 + 1)*EE;
    const __half* bH = WHp + (size_t)n0*EE;
    const __half* bL = WLp + (size_t)n0*EE;

    float acc[4][4][4] = {};
    int wm = wid & 1, wn = wid >> 1;
    int mrow0 = wm*64, ncol0 = wn*32;

    ld_tile32(sb,         aF, EE, 128);
    ld_tile32(sb + 10240, bH, EE, 128);
    ld_tile32(sb + 20480, bL, EE, 128);
    CPA_COMMIT();
    int buf = 0;
    for (int ch = 0; ch < 32; ch++) {
        if (ch + 1 < 32) {
            uint32_t nb = sb + (buf^1)*30720;
            int kt = (ch + 1) * 32;
            ld_tile32(nb,         aF + kt, EE, 128);
            ld_tile32(nb + 10240, bH + kt, EE, 128);
            ld_tile32(nb + 20480, bL + kt, EE, 128);
            CPA_COMMIT();
            CPA_WAIT1();
        } else CPA_WAIT0();
        __syncthreads();
        uint32_t base = sb + buf*30720;
        wmma_step2h<4>(acc, base, base+10240, base+20480, mrow0, ncol0, 0,  lane);
        wmma_step2h<4>(acc, base, base+10240, base+20480, mrow0, ncol0, 16, lane);
        __syncthreads();
        buf ^= 1;
    }

    int rbase = mrow0 + (lane >> 2);
    int cbase = ncol0 + (lane & 3)*2;
    const float inv64 = 1.0f/64.0f;
    #pragma unroll
    for (int mi = 0; mi < 4; mi++)
        #pragma unroll
        for (int half = 0; half < 2; half++) {
            int i = i0 + rbase + mi*16 + half*8;
            #pragma unroll
            for (int nj = 0; nj < 4; nj++) {
                int col = n0 + cbase + nj*8;
                int h2 = col >> 6, d2 = col & 63;
                float v0 = acc[mi][nj][half*2]*inv64   + bias[col];
                float v1 = acc[mi][nj][half*2+1]*inv64 + bias[col+1];
                size_t qi = ((size_t)(b_*HH + h2)*SQ + i)*DH + d2;
                size_t ti = ((size_t)(b_*HH + h2)*DH + d2)*SQ + i;
                if (w == 0) {
                    *(float2*)&QS[qi] = make_float2(v0, v1);
                    *(uint32_t*)&Qh[qi] = packh2(v0, v1);
                } else if (w == 1) {
                    *(float2*)&KS[qi] = make_float2(v0, v1);
                    *(uint32_t*)&Kh16[qi] = packh2(v0, v1);
                } else if (w == 2) {
                    *(float2*)&VS[qi] = make_float2(v0, v1);
                    VTh[ti] = __float2half(v0);
                    VTh[ti + SQ] = __float2half(v1);
                } else {
                    CPTh[ti] = __float2half(v0);
                    CPTh[ti + SQ] = __float2half(v1);
                }
            }
        }
}

// ============================================================
// fused attention: S = Qh·Kh (fp16 single-pass) -> raw l to attn,
// dual online softmax, O1 += P1@V, O2 += P2@CP (fp16 single-pass).
// grid(8,64) block 256. smem: Q 20480 + 2 x 30720 = 81920
// ============================================================
__global__ void __launch_bounds__(256) fused_attn(float* __restrict__ attn)
{
    extern __shared__ uint8_t dyn[];
    uint32_t sQ = s2u(dyn);
    uint32_t sT = sQ + 20480;
    int tid = threadIdx.x, wid = tid >> 5, lane = tid & 31;
    int bh = blockIdx.y;
    int m0 = blockIdx.x * 128;
    int mrow0 = wid * 16;
    int g = lane >> 2, tig = lane & 3;
    int r0 = mrow0 + g, r1 = r0 + 8;
    int gr0 = m0 + r0, gr1 = m0 + r1;

    float qn0 = QN2[(size_t)bh*SQ + gr0], qn1 = QN2[(size_t)bh*SQ + gr1];
    float cn = CN2[bh];
    float sc0 = rsqrtf(64.0f * qn0), sc1r = rsqrtf(64.0f * qn1);
    float rr0 = rsqrtf(qn0 * cn), rr1 = rsqrtf(qn1 * cn);

    float* attnb = attn + (size_t)bh*SQ*SQ;
    const float* cqrow = CQg + (size_t)bh*SQ;

    {
        const __half* qh = Qh + (size_t)bh*SQ*DH + (size_t)m0*DH;
        ld_tile32(sQ,         qh,      DH, 128);
        ld_tile32(sQ + 10240, qh + 32, DH, 128);
        CPA_COMMIT();
    }

    #define FLOAD(bb, jt) do { \
        int j0_ = (jt) * 64; \
        const __half* kh_ = Kh16 + (size_t)bh*SQ*DH + (size_t)j0_*DH; \
        const __half* vh_ = VTh + (size_t)bh*DH*SQ + j0_; \
        const __half* ph_ = CPTh + (size_t)bh*DH*SQ + j0_; \
        ld_tile32((bb),        kh_,      DH, 64); \
        ld_tile32((bb)+5120,   kh_ + 32, DH, 64); \
        ld_tile32((bb)+10240,  vh_,      SQ, 64); \
        ld_tile32((bb)+15360,  vh_ + 32, SQ, 64); \
        ld_tile32((bb)+20480,  ph_,      SQ, 64); \
        ld_tile32((bb)+25600,  ph_ + 32, SQ, 64); \
        CPA_COMMIT(); \
    } while (0)

    float O1[8][4] = {}, O2[8][4] = {};
    float m1_0 = -1e30f, m1_1 = -1e30f, m2_0 = -1e30f, m2_1 = -1e30f;
    float s1_0 = 0.f, s1_1 = 0.f, s2_0 = 0.f, s2_1 = 0.f;

    FLOAD(sT, 0);
    int buf = 0;
    for (int jt = 0; jt < 16; jt++) {
        if (jt + 1 < 16) { FLOAD(sT + (buf^1)*30720, jt + 1); CPA_WAIT1(); }
        else CPA_WAIT0();
        __syncthreads();
        uint32_t bb = sT + buf*30720;
        int j0 = jt * 64;

        // ---- S = Qh · Kh (single-pass) ----
        float S[8][4] = {};
        #pragma unroll
        for (int kk = 0; kk < 64; kk += 16) {
            int cch = kk >> 5, k0 = kk & 16;
            uint32_t aQ = sQ + cch*10240;
            uint32_t a0, a1, a2, a3;
            uint32_t offA = ((uint32_t)(mrow0 + (lane & 15))*40u + (uint32_t)k0 + ((lane >> 4) << 3)) * 2u;
            LDSM4(a0, a1, a2, a3, aQ + offA);
            uint32_t bHf[4][2], bHf2[4][2];
            uint32_t kb = bb + cch*5120;
            ldB32(bHf,  kb, 0,  k0, lane);
            ldB32(bHf2, kb, 32, k0, lane);
            #pragma unroll
            for (int f = 0; f < 4; f++) {
                mma16816h(S[f],   a0, a1, a2, a3, bHf[f][0],  bHf[f][1]);
                mma16816h(S[f+4], a0, a1, a2, a3, bHf2[f][0], bHf2[f][1]);
            }
        }

        // ---- scale to l, store raw, track maxes ----
        float cqv[8][2];
        float lmax0 = -1e30f, lmax1 = -1e30f, l2max0 = -1e30f, l2max1 = -1e30f;
        #pragma unroll
        for (int f = 0; f < 8; f++) {
            int col = j0 + f*8 + tig*2;
            float2 cq = *(const float2*)&cqrow[col];
            cqv[f][0] = cq.x; cqv[f][1] = cq.y;
            S[f][0] *= sc0;  S[f][1] *= sc0;
            S[f][2] *= sc1r; S[f][3] *= sc1r;
            *(float2*)&attnb[(size_t)gr0*SQ + col] = make_float2(S[f][0], S[f][1]);
            *(float2*)&attnb[(size_t)gr1*SQ + col] = make_float2(S[f][2], S[f][3]);
            lmax0 = fmaxf(lmax0, fmaxf(S[f][0], S[f][1]));
            lmax1 = fmaxf(lmax1, fmaxf(S[f][2], S[f][3]));
            l2max0 = fmaxf(l2max0, fmaxf(S[f][0]*cq.x*rr0, S[f][1]*cq.y*rr0));
            l2max1 = fmaxf(l2max1, fmaxf(S[f][2]*cq.x*rr1, S[f][3]*cq.y*rr1));
        }
        #pragma unroll
        for (int o = 1; o <= 2; o <<= 1) {
            lmax0  = fmaxf(lmax0,  __shfl_xor_sync(0xffffffffu, lmax0,  o));
            lmax1  = fmaxf(lmax1,  __shfl_xor_sync(0xffffffffu, lmax1,  o));
            l2max0 = fmaxf(l2max0, __shfl_xor_sync(0xffffffffu, l2max0, o));
            l2max1 = fmaxf(l2max1, __shfl_xor_sync(0xffffffffu, l2max1, o));
        }
        float m1n0 = fmaxf(m1_0, lmax0),  m1n1 = fmaxf(m1_1, lmax1);
        float m2n0 = fmaxf(m2_0, l2max0), m2n1 = fmaxf(m2_1, l2max1);
        float f10 = __expf(m1_0 - m1n0), f11 = __expf(m1_1 - m1n1);
        float f20 = __expf(m2_0 - m2n0), f21 = __expf(m2_1 - m2n1);
        m1_0 = m1n0; m1_1 = m1n1; m2_0 = m2n0; m2_1 = m2n1;
        #pragma unroll
        for (int f = 0; f < 8; f++) {
            O1[f][0] *= f10; O1[f][1] *= f10; O1[f][2] *= f11; O1[f][3] *= f11;
            O2[f][0] *= f20; O2[f][1] *= f20; O2[f][2] *= f21; O2[f][3] *= f21;
        }

        // ---- path 1: O1 += P1 @ V (single-pass) ----
        {
            uint32_t ph01[8], ph23[8];
            float ps0 = 0.f, ps1 = 0.f;
            #pragma unroll
            for (int f = 0; f < 8; f++) {
                float p0 = __expf(S[f][0] - m1n0), p1v = __expf(S[f][1] - m1n0);
                float p2v = __expf(S[f][2] - m1n1), p3v = __expf(S[f][3] - m1n1);
                ps0 += p0 + p1v; ps1 += p2v + p3v;
                ph01[f] = packh2(p0, p1v);
                ph23[f] = packh2(p2v, p3v);
            }
            #pragma unroll
            for (int o = 1; o <= 2; o <<= 1) {
                ps0 += __shfl_xor_sync(0xffffffffu, ps0, o);
                ps1 += __shfl_xor_sync(0xffffffffu, ps1, o);
            }
            s1_0 = s1_0 * f10 + ps0; s1_1 = s1_1 * f11 + ps1;
            #pragma unroll
            for (int kk = 0; kk < 64; kk += 16) {
                int cch = kk >> 5, k0 = kk & 16;
                int gp = kk >> 3;
                uint32_t vb = bb + 10240 + cch*5120;
                uint32_t bHf[4][2], bHf2[4][2];
                ldB32(bHf,  vb, 0,  k0, lane);
                ldB32(bHf2, vb, 32, k0, lane);
                uint32_t a0 = ph01[gp], a1 = ph23[gp], a2 = ph01[gp+1], a3 = ph23[gp+1];
                #pragma unroll
                for (int f = 0; f < 4; f++) {
                    mma16816h(O1[f],   a0, a1, a2, a3, bHf[f][0],  bHf[f][1]);
                    mma16816h(O1[f+4], a0, a1, a2, a3, bHf2[f][0], bHf2[f][1]);
                }
            }
        }

        // ---- path 2: O2 += P2 @ CP (single-pass) ----
        {
            uint32_t ph01[8], ph23[8];
            float ps0 = 0.f, ps1 = 0.f;
            #pragma unroll
            for (int f = 0; f < 8; f++) {
                float p0 = __expf(S[f][0]*cqv[f][0]*rr0 - m2n0);
                float p1v = __expf(S[f][1]*cqv[f][1]*rr0 - m2n0);
                float p2v = __expf(S[f][2]*cqv[f][0]*rr1 - m2n1);
                float p3v = __expf(S[f][3]*cqv[f][1]*rr1 - m2n1);
                ps0 += p0 + p1v; ps1 += p2v + p3v;
                ph01[f] = packh2(p0, p1v);
                ph23[f] = packh2(p2v, p3v);
            }
            #pragma unroll
            for (int o = 1; o <= 2; o <<= 1) {
                ps0 += __shfl_xor_sync(0xffffffffu, ps0, o);
                ps1 += __shfl_xor_sync(0xffffffffu, ps1, o);
            }
            s2_0 = s2_0 * f20 + ps0; s2_1 = s2_1 * f21 + ps1;
            #pragma unroll
            for (int kk = 0; kk < 64; kk += 16) {
                int cch = kk >> 5, k0 = kk & 16;
                int gp = kk >> 3;
                uint32_t pb = bb + 20480 + cch*5120;
                uint32_t bHf[4][2], bHf2[4][2];
                ldB32(bHf,  pb, 0,  k0, lane);
                ldB32(bHf2, pb, 32, k0, lane);
                uint32_t a0 = ph01[gp], a1 = ph23[gp], a2 = ph01[gp+1], a3 = ph23[gp+1];
                #pragma unroll
                for (int f = 0; f < 4; f++) {
                    mma16816h(O2[f],   a0, a1, a2, a3, bHf[f][0],  bHf[f][1]);
                    mma16816h(O2[f+4], a0, a1, a2, a3, bHf2[f][0], bHf2[f][1]);
                }
            }
        }
        __syncthreads();
        buf ^= 1;
    }
    #undef FLOAD

    // ---- epilogue: values rows + stats into dead scratch ----
    int b_ = bh / HH, h_ = bh % HH;
    float is10 = 1.f/s1_0, is11 = 1.f/s1_1, is20 = 1.f/s2_0, is21 = 1.f/s2_1;
    size_t ob0 = (size_t)(b_*SS + 1 + gr0)*EE + h_*DH;
    size_t ob1 = (size_t)(b_*SS + 1 + gr1)*EE + h_*DH;
    #pragma unroll
    for (int f = 0; f < 8; f++) {
        int d = f*8 + tig*2;
        float v0 = O1[f][0]*is10 + O2[f][0]*is20;
        float v1 = O1[f][1]*is10 + O2[f][1]*is20;
        float v2 = O1[f][2]*is11 + O2[f][2]*is21;
        float v3 = O1[f][3]*is11 + O2[f][3]*is21;
        *(uint32_t*)&VALSh[ob0 + d] = packh2(v0, v1);
        *(uint32_t*)&VALSh[ob1 + d] = packh2(v2, v3);
    }
    // QN2[row] <- row max, QS[row] <- 1/rowsum (dead scratch reuse)
    if (tig == 0) {
        QN2[(size_t)bh*SQ + gr0] = m1_0; QS[(size_t)bh*SQ + gr0] = is10;
        QN2[(size_t)bh*SQ + gr1] = m1_1; QS[(size_t)bh*SQ + gr1] = is11;
    }
}

// ============================================================
// attn_fix: attn = exp(l - M)/S in place. one row per block.
// ============================================================
__global__ void attn_fix(float* __restrict__ attn) {
    int row = blockIdx.x;
    float m = QN2[row], si = QS[row];
    float4* p = (float4*)(attn + (size_t)row*SQ);
    float4 v = p[threadIdx.x];
    v.x = __expf(v.x - m)*si;
    v.y = __expf(v.y - m)*si;
    v.z = __expf(v.z - m)*si;
    v.w = __expf(v.w - m)*si;
    p[threadIdx.x] = v;
}

// ============================================================
// out: VALS(f16) @ (64Wo)^T/64 + bo. fp16 2-pass. grid(8,33)
// ============================================================
__global__ void __launch_bounds__(256) out_mm(const float* __restrict__ bo,
                                             float* __restrict__ out)
{
    extern __shared__ uint8_t dyn[];
    uint32_t sb = s2u(dyn);
    int tid = threadIdx.x, wid = tid >> 5, lane = tid & 31;
    int m0 = blockIdx.y * 128, n0 = blockIdx.x * 128;

    const __half* aF = VALSh + (size_t)m0*EE;
    const __half* bH = WoHh + (size_t)n0*EE;
    const __half* bL = WoLh + (size_t)n0*EE;

    float acc[4][4][4] = {};
    int wm = wid & 1, wn = wid >> 1;
    int mrow0 = wm*64, ncol0 = wn*32;

    ld_tile32(sb,         aF, EE, 128);
    ld_tile32(sb + 10240, bH, EE, 128);
    ld_tile32(sb + 20480, bL, EE, 128);
    CPA_COMMIT();
    int buf = 0;
    for (int ch = 0; ch < 32; ch++) {
        if (ch + 1 < 32) {
            uint32_t nb = sb + (buf^1)*30720;
            int kt = (ch + 1) * 32;
            ld_tile32(nb,         aF + kt, EE, 128);
            ld_tile32(nb + 10240, bH + kt, EE, 128);
            ld_tile32(nb + 20480, bL + kt, EE, 128);
            CPA_COMMIT();
            CPA_WAIT1();
        } else CPA_WAIT0();
        __syncthreads();
        uint32_t base = sb + buf*30720;
        wmma_step2h<4>(acc, base, base+10240, base+20480, mrow0, ncol0, 0,  lane);
        wmma_step2h<4>(acc, base, base+10240, base+20480, mrow0, ncol0, 16, lane);
        __syncthreads();
        buf ^= 1;
    }

    int rbase = mrow0 + (lane >> 2);
    int cbase = ncol0 + (lane & 3)*2;
    const float inv64 = 1.0f/64.0f;
    #pragma unroll
    for (int mi = 0; mi < 4; mi++)
        #pragma unroll
        for (int half = 0; half < 2; half++) {
            int mr = m0 + rbase + mi*16 + half*8;
            if (mr >= MROWS_OUT) continue;
            #pragma unroll
            for (int nj = 0; nj < 4; nj++) {
                int col = n0 + cbase + nj*8;
                *(float2*)&out[(size_t)mr*EE + col] =
                    make_float2(acc[mi][nj][half*2]*inv64 + bo[col],
                                acc[mi][nj][half*2+1]*inv64 + bo[col+1]);
            }
        }
}

// ============================================================
// cls token projection + CN2. grid BH, block 64
// ============================================================
__global__ void clsproj_kernel(const float* __restrict__ x,
                               const float* __restrict__ Wq,
                               const float* __restrict__ bq) {
    int bh = blockIdx.x;
    int b_ = bh / HH, h_ = bh % HH;
    int d  = threadIdx.x;
    int j  = h_*DH + d;
    const float* xr = x  + (size_t)(b_*SS)*EE;
    const float* wr = Wq + (size_t)j*EE;
    float s = 0.f;
    for (int e = 0; e < EE; e += 4) {
        float4 xv = *(const float4*)(xr + e);
        float4 wv = *(const float4*)(wr + e);
        s += xv.x*wv.x + xv.y*wv.y + xv.z*wv.z + xv.w*wv.w;
    }
    s += bq[j];
    CVEC[bh*DH + d] = s;
    __shared__ float red[64];
    red[d] = s*s; __syncthreads();
    for (int o = 32; o > 0; o >>= 1) { if (d < o) red[d] += red[d+o]; __syncthreads(); }
    if (d == 0) CN2[bh] = fmaxf(red[0], EPSF);
}

// ============================================================
// per-row q stats: QN2 and CQ. grid BH*SQ/8, block 256
// ============================================================
__global__ void qstats_kernel() {
    int row  = blockIdx.x*8 + (threadIdx.x >> 5);
    int lane = threadIdx.x & 31;
    int bh   = row >> 10;
    const float* qr = QS   + (size_t)row*DH;
    const float* cv = CVEC + bh*DH;
    float n2 = 0.f, cq = 0.f;
    #pragma unroll
    for (int d = lane; d < DH; d += 32) {
        float qv = qr[d];
        n2 += qv*qv;
        cq += qv*cv[d];
    }
    #pragma unroll
    for (int o = 16; o > 0; o >>= 1) {
        n2 += __shfl_xor_sync(0xffffffffu, n2, o);
        cq += __shfl_xor_sync(0xffffffffu, cq, o);
    }
    if (lane == 0) { QN2[row] = fmaxf(n2, EPSF); CQg[row] = cq; }
}

// ============================================================
// cls path: ck softmax -> cls_out row (fp16 into VALS). grid BH, block 256
// ============================================================
__global__ void cls_kernel() {
    int bh = blockIdx.x;
    int tid = threadIdx.x;
    const float* Kp = KS + (size_t)bh*SQ*DH;
    const float* Vp = VS + (size_t)bh*SQ*DH;
    __shared__ float p_s[SQ];
    __shared__ float red[256];
    __shared__ float c_s[DH];
    if (tid < DH) c_s[tid] = CVEC[bh*DH + tid];
    __syncthreads();

    float scale = rsqrtf(64.0f * CN2[bh]);
    float lo[4];
    #pragma unroll
    for (int p = 0; p < 4; p++) {
        int j = tid + p*256;
        const float* kr = Kp + (size_t)j*DH;
        float s = 0.f;
        #pragma unroll
        for (int d = 0; d < DH; d += 4) {
            float4 kv = *(const float4*)(kr + d);
            s += c_s[d]*kv.x + c_s[d+1]*kv.y + c_s[d+2]*kv.z + c_s[d+3]*kv.w;
        }
        lo[p] = s * scale;
    }
    float m = fmaxf(fmaxf(lo[0],lo[1]), fmaxf(lo[2],lo[3]));
    red[tid] = m; __syncthreads();
    #pragma unroll
    for (int o = 128; o > 0; o >>= 1) { if (tid < o) red[tid] = fmaxf(red[tid], red[tid+o]); __syncthreads(); }
    m = red[0]; __syncthreads();
    float e[4], s = 0.f;
    #pragma unroll
    for (int p = 0; p < 4; p++) { e[p] = __expf(lo[p] - m); s += e[p]; }
    red[tid] = s; __syncthreads();
    #pragma unroll
    for (int o = 128; o > 0; o >>= 1) { if (tid < o) red[tid] += red[tid+o]; __syncthreads(); }
    float inv = 1.0f / red[0]; __syncthreads();
    #pragma unroll
    for (int p = 0; p < 4; p++) p_s[tid + p*256] = e[p]*inv;
    __syncthreads();

    int d = tid & 63, g = tid >> 6;
    float acc = 0.f;
    for (int j = g*256; j < (g+1)*256; j++) acc += p_s[j] * Vp[(size_t)j*DH + d];
    red[tid] = acc; __syncthreads();
    if (g == 0) {
        float rsum = red[tid] + red[tid+64] + red[tid+128] + red[tid+192];
        int b_ = bh / HH, h_ = bh % HH;
        size_t idx = (size_t)(b_*SS)*EE + h_*DH + d;
        VALSh[idx] = __float2half(rsum);
    }
}

extern "C" void kernel_launch(void* const* d_in, const int* in_sizes, int n_in,
                              void* d_out, int out_size) {
    const float* x  = (const float*)d_in[0];
    const float* Wq = (const float*)d_in[1];
    const float* bq = (const float*)d_in[2];
    const float* Wk = (const float*)d_in[3];
    const float* bk = (const float*)d_in[4];
    const float* Wv = (const float*)d_in[5];
    const float* bv = (const float*)d_in[6];
    const float* Wo = (const float*)d_in[7];
    const float* bo = (const float*)d_in[8];
    const float* Wc = (const float*)d_in[9];
    const float* bc = (const float*)d_in[10];

    float* out  = (float*)d_out;
    float* attn = out + (size_t)BB*SS*EE;

    cudaFuncSetAttribute(proj_mm,    cudaFuncAttributeMaxDynamicSharedMemorySize, 61440);
    cudaFuncSetAttribute(out_mm,     cudaFuncAttributeMaxDynamicSharedMemorySize, 61440);
    cudaFuncSetAttribute(fused_attn, cudaFuncAttributeMaxDynamicSharedMemorySize, 81920);

    __half *xh, *wqh, *wql, *wkh, *wkl, *wvh, *wvl, *wch, *wcl, *woh, *wol;
    cudaGetSymbolAddress((void**)&xh, Xh);
    cudaGetSymbolAddress((void**)&wqh, WqHh); cudaGetSymbolAddress((void**)&wql, WqLh);
    cudaGetSymbolAddress((void**)&wkh, WkHh); cudaGetSymbolAddress((void**)&wkl, WkLh);
    cudaGetSymbolAddress((void**)&wvh, WvHh); cudaGetSymbolAddress((void**)&wvl, WvLh);
    cudaGetSymbolAddress((void**)&wch, WcHh); cudaGetSymbolAddress((void**)&wcl, WcLh);
    cudaGetSymbolAddress((void**)&woh, WoHh); cudaGetSymbolAddress((void**)&wol, WoLh);

    int nx4 = BB*SS*EE/4, nw4 = EE*EE/4;
    // 1: x -> fp16
    convXh_kernel<<<(nx4+255)/256, 256>>>(x, xh, nx4);
    // 2: Wq + Wk -> fp16 hi/lo x64
    convW2_kernel<<<dim3((nw4+255)/256, 2), 256>>>(Wq, wqh, wql, Wk, wkh, wkl, nw4);
    // 3: Wv + Wc
    convW2_kernel<<<dim3((nw4+255)/256, 2), 256>>>(Wv, wvh, wvl, Wc, wch, wcl, nw4);
    // 4: proj (ncu capture target)
    proj_mm<<<dim3(8,32,4), 256, 61440>>>(bq, bk, bv, bc);
    // 5: Wo
    convW_kernel<<<(nw4+255)/256, 256>>>(Wo, woh, wol, nw4);
    // 6-7: cls projection + q stats
    clsproj_kernel<<<BH, 64>>>(x, Wq, bq);
    qstats_kernel<<<BH*SQ/8, 256>>>();
    // 8: fused attention (stats -> QN2/QS dead scratch)
    fused_attn<<<dim3(8,BH), 256, 81920>>>(attn);
    // 9: attn normalization (flat bandwidth-bound kernel)
    attn_fix<<<BH*SQ, 256>>>(attn);
    // 10: cls output row
    cls_kernel<<<BH, 256>>>();
    // 11: output projection
    out_mm<<<dim3(8,33), 256, 61440>>>(bo, out);
}

// round 15
// speedup vs baseline: 1.5559x; 1.1749x over previous
#include <cuda_runtime.h>
#include <cuda_bf16.h>
#include <cuda_fp16.h>
#include <cstdint>

#define BB 4
#define SS 1025
#define SQ 1024
#define EE 1024
#define HH 16
#define DH 64
#define BH (BB*HH)
#define EPSF 1e-5f
#define MROWS_OUT (BB*SS)     // 4100
#define MTILES_OUT 33         // 33*128 = 4224

typedef __nv_bfloat16 bf16;

// ---------------- device scratch (allocation-free) ----------------
// After fused_attn: QN2[row] = final row max (M), QS[row] = 1/rowsum (S)
// for attn_fix (both arrays dead for their original purpose by then).
__device__ float QS[BH*SQ*DH];          // fp32 q (qstats) -> later 1/rowsum
__device__ float KS[BH*SQ*DH];          // fp32 k  (cls path)
__device__ float VS[BH*SQ*DH];          // fp32 v  (cls path)
__device__ __half Xh[BB*SS*EE];                       // x single fp16
__device__ __half WqHh[EE*EE], WkHh[EE*EE];           // 64*W fp16 (single)
__device__ __half WvHh[EE*EE], WcHh[EE*EE];
__device__ __half WoHh[EE*EE];
__device__ __half Qh[BH*SQ*DH];                       // q single fp16
__device__ __half Kh16[BH*SQ*DH];                     // k single fp16
__device__ __half VTh[BH*DH*SQ];                      // V^T single fp16
__device__ __half CPTh[BH*DH*SQ];                     // cls_proj^T single fp16
__device__ __half VALSh[(size_t)MTILES_OUT*128*EE];   // values, single fp16
__device__ float CVEC[BH*DH];
__device__ float CN2[BH];
__device__ float QN2[BH*SQ];            // |q|^2 -> later row max
__device__ float CQg[BH*SQ];

// ---------------- warp-mma helpers ----------------
__device__ __forceinline__ uint32_t s2u(const void* p) {
    uint32_t a;
    asm("{ .reg .u64 t; cvta.to.shared.u64 t, %1; cvt.u32.u64 %0, t; }" : "=r"(a) : "l"(p));
    return a;
}
#define LDSM4(R0,R1,R2,R3,addr) \
    asm volatile("ldmatrix.sync.aligned.m8n8.x4.shared.b16 {%0,%1,%2,%3}, [%4];" \
        : "=r"(R0),"=r"(R1),"=r"(R2),"=r"(R3) : "r"(addr))

__device__ __forceinline__ void mma16816h(float* c, uint32_t a0, uint32_t a1,
                                          uint32_t a2, uint32_t a3,
                                          uint32_t b0, uint32_t b1) {
    asm volatile(
        "mma.sync.aligned.m16n8k16.row.col.f32.f16.f16.f32 "
        "{%0,%1,%2,%3}, {%4,%5,%6,%7}, {%8,%9}, {%0,%1,%2,%3};"
        : "+f"(c[0]), "+f"(c[1]), "+f"(c[2]), "+f"(c[3])
        : "r"(a0), "r"(a1), "r"(a2), "r"(a3), "r"(b0), "r"(b1));
}

// fp16 single-pass k16 step: A single, B single. MT*16 x 32 warp tile.
template<int MT>
__device__ __forceinline__ void wmma_step1h(float (*acc)[4][4],
    uint32_t aB, uint32_t bB,
    int mrow0, int ncol0, int k0, int lane)
{
    uint32_t aF[MT][4];
    #pragma unroll
    for (int mi = 0; mi < MT; mi++) {
        uint32_t off = ((uint32_t)(mrow0 + mi*16 + (lane & 15))*40u + (uint32_t)k0 + ((lane >> 4) << 3)) * 2u;
        LDSM4(aF[mi][0], aF[mi][1], aF[mi][2], aF[mi][3], aB + off);
    }
    uint32_t bHf[4][2];
    int j = lane >> 3;
    #pragma unroll
    for (int p = 0; p < 2; p++) {
        uint32_t off = ((uint32_t)(ncol0 + p*16 + ((j >> 1) << 3) + (lane & 7))*40u + (uint32_t)k0 + ((j & 1) << 3)) * 2u;
        uint32_t r0, r1, r2, r3;
        LDSM4(r0, r1, r2, r3, bB + off);
        bHf[p*2][0] = r0; bHf[p*2][1] = r1; bHf[p*2+1][0] = r2; bHf[p*2+1][1] = r3;
    }
    #pragma unroll
    for (int mi = 0; mi < MT; mi++)
        #pragma unroll
        for (int nj = 0; nj < 4; nj++)
            mma16816h(acc[mi][nj], aF[mi][0], aF[mi][1], aF[mi][2], aF[mi][3], bHf[nj][0], bHf[nj][1]);
}

// 4 n8-frags (32 cols) from smem tile (stride 40)
__device__ __forceinline__ void ldB32(uint32_t (*bf)[2], uint32_t base, int n0_, int k0, int lane) {
    int j = lane >> 3;
    #pragma unroll
    for (int p = 0; p < 2; p++) {
        uint32_t off = ((uint32_t)(n0_ + p*16 + ((j >> 1) << 3) + (lane & 7))*40u + (uint32_t)k0 + ((j & 1) << 3)) * 2u;
        uint32_t r0, r1, r2, r3;
        LDSM4(r0, r1, r2, r3, base + off);
        bf[p*2][0] = r0; bf[p*2][1] = r1; bf[p*2+1][0] = r2; bf[p*2+1][1] = r3;
    }
}

// load nrows x 32 b16 elems into smem tile (stride 40 elems) via cp.async
__device__ __forceinline__ void ld_tile32(uint32_t sdst, const void* gv, size_t rstride, int nrows) {
    const __half* g = (const __half*)gv;
    int tid = threadIdx.x;
    int tot = nrows * 4;
    for (int u = tid; u < tot; u += 256) {
        int r = u >> 2, c = u & 3;
        uint32_t dst = sdst + (uint32_t)(r*80 + c*16);
        const __half* src = g + (size_t)r * rstride + (c << 3);
        asm volatile("cp.async.cg.shared.global [%0], [%1], 16;" :: "r"(dst), "l"(src) : "memory");
    }
}
#define CPA_COMMIT() asm volatile("cp.async.commit_group;" ::: "memory")
#define CPA_WAIT1()  asm volatile("cp.async.wait_group 1;" ::: "memory")
#define CPA_WAIT0()  asm volatile("cp.async.wait_group 0;" ::: "memory")

__device__ __forceinline__ uint32_t packh2(float a, float b) {
    __half2 t = __floats2half2_rn(a, b);
    return *(uint32_t*)&t;
}

// ============================================================
// conversions (fp32 -> single fp16; W scaled x64)
// ============================================================
__global__ void convXh_kernel(const float* __restrict__ s, __half* __restrict__ h, int n4) {
    int i = blockIdx.x * 256 + threadIdx.x;
    if (i >= n4) return;
    float4 v = ((const float4*)s)[i];
    uint2 hp;
    hp.x = packh2(v.x, v.y); hp.y = packh2(v.z, v.w);
    ((uint2*)h)[i] = hp;
}
__device__ __forceinline__ void convW_body(const float* __restrict__ s,
                                           __half* __restrict__ h, int i) {
    float4 v = ((const float4*)s)[i];
    uint2 hp;
    hp.x = packh2(v.x*64.f, v.y*64.f); hp.y = packh2(v.z*64.f, v.w*64.f);
    ((uint2*)h)[i] = hp;
}
__global__ void convW_kernel(const float* __restrict__ s, __half* __restrict__ h, int n4) {
    int i = blockIdx.x * 256 + threadIdx.x;
    if (i >= n4) return;
    convW_body(s, h, i);
}
__global__ void convW2_kernel(const float* __restrict__ s0, __half* __restrict__ h0,
                              const float* __restrict__ s1, __half* __restrict__ h1, int n4) {
    int i = blockIdx.x * 256 + threadIdx.x;
    if (i >= n4) return;
    if (blockIdx.y == 0) convW_body(s0, h0, i);
    else                 convW_body(s1, h1, i);
}

// ============================================================
// proj: 128x128 tile of (x @ (64W)^T)/64 + b. fp16 single-pass. grid(8,32,4)
// smem: 2 x 2 tiles x 10240 = 40960
// ============================================================
__global__ void __launch_bounds__(256) proj_mm(
    const float* __restrict__ b0, const float* __restrict__ b1,
    const float* __restrict__ b2, const float* __restrict__ b3)
{
    extern __shared__ uint8_t dyn[];
    uint32_t sb = s2u(dyn);
    int tid = threadIdx.x, wid = tid >> 5, lane = tid & 31;

    int w = blockIdx.z;
    const __half* WHp = (w==0)?WqHh:(w==1)?WkHh:(w==2)?WvHh:WcHh;
    const float* bias = (w==0)?b0:(w==1)?b1:(w==2)?b2:b3;

    int m0 = blockIdx.y * 128, n0 = blockIdx.x * 128;
    int b_ = m0 >> 10, i0 = m0 & 1023;

    const __half* aF = Xh + (size_t)(b_*SS + i0 + 1)*EE;
    const __half* bH = WHp + (size_t)n0*EE;

    float acc[4][4][4] = {};
    int wm = wid & 1, wn = wid >> 1;
    int mrow0 = wm*64, ncol0 = wn*32;

    ld_tile32(sb,         aF, EE, 128);
    ld_tile32(sb + 10240, bH, EE, 128);
    CPA_COMMIT();
    int buf = 0;
    for (int ch = 0; ch < 32; ch++) {
        if (ch + 1 < 32) {
            uint32_t nb = sb + (buf^1)*20480;
            int kt = (ch + 1) * 32;
            ld_tile32(nb,         aF + kt, EE, 128);
            ld_tile32(nb + 10240, bH + kt, EE, 128);
            CPA_COMMIT();
            CPA_WAIT1();
        } else CPA_WAIT0();
        __syncthreads();
        uint32_t base = sb + buf*20480;
        wmma_step1h<4>(acc, base, base+10240, mrow0, ncol0, 0,  lane);
        wmma_step1h<4>(acc, base, base+10240, mrow0, ncol0, 16, lane);
        __syncthreads();
        buf ^= 1;
    }

    int rbase = mrow0 + (lane >> 2);
    int cbase = ncol0 + (lane & 3)*2;
    const float inv64 = 1.0f/64.0f;
    #pragma unroll
    for (int mi = 0; mi < 4; mi++)
        #pragma unroll
        for (int half = 0; half < 2; half++) {
            int i = i0 + rbase + mi*16 + half*8;
            #pragma unroll
            for (int nj = 0; nj < 4; nj++) {
                int col = n0 + cbase + nj*8;
                int h2 = col >> 6, d2 = col & 63;
                float v0 = acc[mi][nj][half*2]*inv64   + bias[col];
                float v1 = acc[mi][nj][half*2+1]*inv64 + bias[col+1];
                size_t qi = ((size_t)(b_*HH + h2)*SQ + i)*DH + d2;
                size_t ti = ((size_t)(b_*HH + h2)*DH + d2)*SQ + i;
                if (w == 0) {
                    *(float2*)&QS[qi] = make_float2(v0, v1);
                    *(uint32_t*)&Qh[qi] = packh2(v0, v1);
                } else if (w == 1) {
                    *(float2*)&KS[qi] = make_float2(v0, v1);
                    *(uint32_t*)&Kh16[qi] = packh2(v0, v1);
                } else if (w == 2) {
                    *(float2*)&VS[qi] = make_float2(v0, v1);
                    VTh[ti] = __float2half(v0);
                    VTh[ti + SQ] = __float2half(v1);
                } else {
                    CPTh[ti] = __float2half(v0);
                    CPTh[ti + SQ] = __float2half(v1);
                }
            }
        }
}

// ============================================================
// fused attention: S = Qh·Kh (fp16 single) -> raw l to attn,
// dual online softmax, O1 += P1@V, O2 += P2@CP (fp16 single).
// grid(8,64) block 256. smem: Q 20480 + 2 x 30720 = 81920
// ============================================================
__global__ void __launch_bounds__(256) fused_attn(float* __restrict__ attn)
{
    extern __shared__ uint8_t dyn[];
    uint32_t sQ = s2u(dyn);
    uint32_t sT = sQ + 20480;
    int tid = threadIdx.x, wid = tid >> 5, lane = tid & 31;
    int bh = blockIdx.y;
    int m0 = blockIdx.x * 128;
    int mrow0 = wid * 16;
    int g = lane >> 2, tig = lane & 3;
    int r0 = mrow0 + g, r1 = r0 + 8;
    int gr0 = m0 + r0, gr1 = m0 + r1;

    float qn0 = QN2[(size_t)bh*SQ + gr0], qn1 = QN2[(size_t)bh*SQ + gr1];
    float cn = CN2[bh];
    float sc0 = rsqrtf(64.0f * qn0), sc1r = rsqrtf(64.0f * qn1);
    float rr0 = rsqrtf(qn0 * cn), rr1 = rsqrtf(qn1 * cn);

    float* attnb = attn + (size_t)bh*SQ*SQ;
    const float* cqrow = CQg + (size_t)bh*SQ;

    {
        const __half* qh = Qh + (size_t)bh*SQ*DH + (size_t)m0*DH;
        ld_tile32(sQ,         qh,      DH, 128);
        ld_tile32(sQ + 10240, qh + 32, DH, 128);
        CPA_COMMIT();
    }

    #define FLOAD(bb, jt) do { \
        int j0_ = (jt) * 64; \
        const __half* kh_ = Kh16 + (size_t)bh*SQ*DH + (size_t)j0_*DH; \
        const __half* vh_ = VTh + (size_t)bh*DH*SQ + j0_; \
        const __half* ph_ = CPTh + (size_t)bh*DH*SQ + j0_; \
        ld_tile32((bb),        kh_,      DH, 64); \
        ld_tile32((bb)+5120,   kh_ + 32, DH, 64); \
        ld_tile32((bb)+10240,  vh_,      SQ, 64); \
        ld_tile32((bb)+15360,  vh_ + 32, SQ, 64); \
        ld_tile32((bb)+20480,  ph_,      SQ, 64); \
        ld_tile32((bb)+25600,  ph_ + 32, SQ, 64); \
        CPA_COMMIT(); \
    } while (0)

    float O1[8][4] = {}, O2[8][4] = {};
    float m1_0 = -1e30f, m1_1 = -1e30f, m2_0 = -1e30f, m2_1 = -1e30f;
    float s1_0 = 0.f, s1_1 = 0.f, s2_0 = 0.f, s2_1 = 0.f;

    FLOAD(sT, 0);
    int buf = 0;
    for (int jt = 0; jt < 16; jt++) {
        if (jt + 1 < 16) { FLOAD(sT + (buf^1)*30720, jt + 1); CPA_WAIT1(); }
        else CPA_WAIT0();
        __syncthreads();
        uint32_t bb = sT + buf*30720;
        int j0 = jt * 64;

        // ---- S = Qh · Kh ----
        float S[8][4] = {};
        #pragma unroll
        for (int kk = 0; kk < 64; kk += 16) {
            int cch = kk >> 5, k0 = kk & 16;
            uint32_t aQ = sQ + cch*10240;
            uint32_t a0, a1, a2, a3;
            uint32_t offA = ((uint32_t)(mrow0 + (lane & 15))*40u + (uint32_t)k0 + ((lane >> 4) << 3)) * 2u;
            LDSM4(a0, a1, a2, a3, aQ + offA);
            uint32_t bHf[4][2], bHf2[4][2];
            uint32_t kb = bb + cch*5120;
            ldB32(bHf,  kb, 0,  k0, lane);
            ldB32(bHf2, kb, 32, k0, lane);
            #pragma unroll
            for (int f = 0; f < 4; f++) {
                mma16816h(S[f],   a0, a1, a2, a3, bHf[f][0],  bHf[f][1]);
                mma16816h(S[f+4], a0, a1, a2, a3, bHf2[f][0], bHf2[f][1]);
            }
        }

        // ---- scale to l, store raw, track maxes ----
        float cqv[8][2];
        float lmax0 = -1e30f, lmax1 = -1e30f, l2max0 = -1e30f, l2max1 = -1e30f;
        #pragma unroll
        for (int f = 0; f < 8; f++) {
            int col = j0 + f*8 + tig*2;
            float2 cq = *(const float2*)&cqrow[col];
            cqv[f][0] = cq.x; cqv[f][1] = cq.y;
            S[f][0] *= sc0;  S[f][1] *= sc0;
            S[f][2] *= sc1r; S[f][3] *= sc1r;
            *(float2*)&attnb[(size_t)gr0*SQ + col] = make_float2(S[f][0], S[f][1]);
            *(float2*)&attnb[(size_t)gr1*SQ + col] = make_float2(S[f][2], S[f][3]);
            lmax0 = fmaxf(lmax0, fmaxf(S[f][0], S[f][1]));
            lmax1 = fmaxf(lmax1, fmaxf(S[f][2], S[f][3]));
            l2max0 = fmaxf(l2max0, fmaxf(S[f][0]*cq.x*rr0, S[f][1]*cq.y*rr0));
            l2max1 = fmaxf(l2max1, fmaxf(S[f][2]*cq.x*rr1, S[f][3]*cq.y*rr1));
        }
        #pragma unroll
        for (int o = 1; o <= 2; o <<= 1) {
            lmax0  = fmaxf(lmax0,  __shfl_xor_sync(0xffffffffu, lmax0,  o));
            lmax1  = fmaxf(lmax1,  __shfl_xor_sync(0xffffffffu, lmax1,  o));
            l2max0 = fmaxf(l2max0, __shfl_xor_sync(0xffffffffu, l2max0, o));
            l2max1 = fmaxf(l2max1, __shfl_xor_sync(0xffffffffu, l2max1, o));
        }
        float m1n0 = fmaxf(m1_0, lmax0),  m1n1 = fmaxf(m1_1, lmax1);
        float m2n0 = fmaxf(m2_0, l2max0), m2n1 = fmaxf(m2_1, l2max1);
        float f10 = __expf(m1_0 - m1n0), f11 = __expf(m1_1 - m1n1);
        float f20 = __expf(m2_0 - m2n0), f21 = __expf(m2_1 - m2n1);
        m1_0 = m1n0; m1_1 = m1n1; m2_0 = m2n0; m2_1 = m2n1;
        #pragma unroll
        for (int f = 0; f < 8; f++) {
            O1[f][0] *= f10; O1[f][1] *= f10; O1[f][2] *= f11; O1[f][3] *= f11;
            O2[f][0] *= f20; O2[f][1] *= f20; O2[f][2] *= f21; O2[f][3] *= f21;
        }

        // ---- path 1: O1 += P1 @ V ----
        {
            uint32_t ph01[8], ph23[8];
            float ps0 = 0.f, ps1 = 0.f;
            #pragma unroll
            for (int f = 0; f < 8; f++) {
                float p0 = __expf(S[f][0] - m1n0), p1v = __expf(S[f][1] - m1n0);
                float p2v = __expf(S[f][2] - m1n1), p3v = __expf(S[f][3] - m1n1);
                ps0 += p0 + p1v; ps1 += p2v + p3v;
                ph01[f] = packh2(p0, p1v);
                ph23[f] = packh2(p2v, p3v);
            }
            #pragma unroll
            for (int o = 1; o <= 2; o <<= 1) {
                ps0 += __shfl_xor_sync(0xffffffffu, ps0, o);
                ps1 += __shfl_xor_sync(0xffffffffu, ps1, o);
            }
            s1_0 = s1_0 * f10 + ps0; s1_1 = s1_1 * f11 + ps1;
            #pragma unroll
            for (int kk = 0; kk < 64; kk += 16) {
                int cch = kk >> 5, k0 = kk & 16;
                int gp = kk >> 3;
                uint32_t vb = bb + 10240 + cch*5120;
                uint32_t bHf[4][2], bHf2[4][2];
                ldB32(bHf,  vb, 0,  k0, lane);
                ldB32(bHf2, vb, 32, k0, lane);
                uint32_t a0 = ph01[gp], a1 = ph23[gp], a2 = ph01[gp+1], a3 = ph23[gp+1];
                #pragma unroll
                for (int f = 0; f < 4; f++) {
                    mma16816h(O1[f],   a0, a1, a2, a3, bHf[f][0],  bHf[f][1]);
                    mma16816h(O1[f+4], a0, a1, a2, a3, bHf2[f][0], bHf2[f][1]);
                }
            }
        }

        // ---- path 2: O2 += P2 @ CP ----
        {
            uint32_t ph01[8], ph23[8];
            float ps0 = 0.f, ps1 = 0.f;
            #pragma unroll
            for (int f = 0; f < 8; f++) {
                float p0 = __expf(S[f][0]*cqv[f][0]*rr0 - m2n0);
                float p1v = __expf(S[f][1]*cqv[f][1]*rr0 - m2n0);
                float p2v = __expf(S[f][2]*cqv[f][0]*rr1 - m2n1);
                float p3v = __expf(S[f][3]*cqv[f][1]*rr1 - m2n1);
                ps0 += p0 + p1v; ps1 += p2v + p3v;
                ph01[f] = packh2(p0, p1v);
                ph23[f] = packh2(p2v, p3v);
            }
            #pragma unroll
            for (int o = 1; o <= 2; o <<= 1) {
                ps0 += __shfl_xor_sync(0xffffffffu, ps0, o);
                ps1 += __shfl_xor_sync(0xffffffffu, ps1, o);
            }
            s2_0 = s2_0 * f20 + ps0; s2_1 = s2_1 * f21 + ps1;
            #pragma unroll
            for (int kk = 0; kk < 64; kk += 16) {
                int cch = kk >> 5, k0 = kk & 16;
                int gp = kk >> 3;
                uint32_t pb = bb + 20480 + cch*5120;
                uint32_t bHf[4][2], bHf2[4][2];
                ldB32(bHf,  pb, 0,  k0, lane);
                ldB32(bHf2, pb, 32, k0, lane);
                uint32_t a0 = ph01[gp], a1 = ph23[gp], a2 = ph01[gp+1], a3 = ph23[gp+1];
                #pragma unroll
                for (int f = 0; f < 4; f++) {
                    mma16816h(O2[f],   a0, a1, a2, a3, bHf[f][0],  bHf[f][1]);
                    mma16816h(O2[f+4], a0, a1, a2, a3, bHf2[f][0], bHf2[f][1]);
                }
            }
        }
        __syncthreads();
        buf ^= 1;
    }
    #undef FLOAD

    // ---- epilogue: values rows + stats into dead scratch ----
    int b_ = bh / HH, h_ = bh % HH;
    float is10 = 1.f/s1_0, is11 = 1.f/s1_1, is20 = 1.f/s2_0, is21 = 1.f/s2_1;
    size_t ob0 = (size_t)(b_*SS + 1 + gr0)*EE + h_*DH;
    size_t ob1 = (size_t)(b_*SS + 1 + gr1)*EE + h_*DH;
    #pragma unroll
    for (int f = 0; f < 8; f++) {
        int d = f*8 + tig*2;
        float v0 = O1[f][0]*is10 + O2[f][0]*is20;
        float v1 = O1[f][1]*is10 + O2[f][1]*is20;
        float v2 = O1[f][2]*is11 + O2[f][2]*is21;
        float v3 = O1[f][3]*is11 + O2[f][3]*is21;
        *(uint32_t*)&VALSh[ob0 + d] = packh2(v0, v1);
        *(uint32_t*)&VALSh[ob1 + d] = packh2(v2, v3);
    }
    // QN2[row] <- row max, QS[row] <- 1/rowsum (dead scratch reuse)
    if (tig == 0) {
        QN2[(size_t)bh*SQ + gr0] = m1_0; QS[(size_t)bh*SQ + gr0] = is10;
        QN2[(size_t)bh*SQ + gr1] = m1_1; QS[(size_t)bh*SQ + gr1] = is11;
    }
}

// ============================================================
// attn_fix: attn = exp(l - M)/S in place. one row per block.
// ============================================================
__global__ void attn_fix(float* __restrict__ attn) {
    int row = blockIdx.x;
    float m = QN2[row], si = QS[row];
    float4* p = (float4*)(attn + (size_t)row*SQ);
    float4 v = p[threadIdx.x];
    v.x = __expf(v.x - m)*si;
    v.y = __expf(v.y - m)*si;
    v.z = __expf(v.z - m)*si;
    v.w = __expf(v.w - m)*si;
    p[threadIdx.x] = v;
}

// ============================================================
// out: VALS(f16) @ (64Wo)^T/64 + bo. fp16 single-pass. grid(8,33)
// ============================================================
__global__ void __launch_bounds__(256) out_mm(const float* __restrict__ bo,
                                             float* __restrict__ out)
{
    extern __shared__ uint8_t dyn[];
    uint32_t sb = s2u(dyn);
    int tid = threadIdx.x, wid = tid >> 5, lane = tid & 31;
    int m0 = blockIdx.y * 128, n0 = blockIdx.x * 128;

    const __half* aF = VALSh + (size_t)m0*EE;
    const __half* bH = WoHh + (size_t)n0*EE;

    float acc[4][4][4] = {};
    int wm = wid & 1, wn = wid >> 1;
    int mrow0 = wm*64, ncol0 = wn*32;

    ld_tile32(sb,         aF, EE, 128);
    ld_tile32(sb + 10240, bH, EE, 128);
    CPA_COMMIT();
    int buf = 0;
    for (int ch = 0; ch < 32; ch++) {
        if (ch + 1 < 32) {
            uint32_t nb = sb + (buf^1)*20480;
            int kt = (ch + 1) * 32;
            ld_tile32(nb,         aF + kt, EE, 128);
            ld_tile32(nb + 10240, bH + kt, EE, 128);
            CPA_COMMIT();
            CPA_WAIT1();
        } else CPA_WAIT0();
        __syncthreads();
        uint32_t base = sb + buf*20480;
        wmma_step1h<4>(acc, base, base+10240, mrow0, ncol0, 0,  lane);
        wmma_step1h<4>(acc, base, base+10240, mrow0, ncol0, 16, lane);
        __syncthreads();
        buf ^= 1;
    }

    int rbase = mrow0 + (lane >> 2);
    int cbase = ncol0 + (lane & 3)*2;
    const float inv64 = 1.0f/64.0f;
    #pragma unroll
    for (int mi = 0; mi < 4; mi++)
        #pragma unroll
        for (int half = 0; half < 2; half++) {
            int mr = m0 + rbase + mi*16 + half*8;
            if (mr >= MROWS_OUT) continue;
            #pragma unroll
            for (int nj = 0; nj < 4; nj++) {
                int col = n0 + cbase + nj*8;
                *(float2*)&out[(size_t)mr*EE + col] =
                    make_float2(acc[mi][nj][half*2]*inv64 + bo[col],
                                acc[mi][nj][half*2+1]*inv64 + bo[col+1]);
            }
        }
}

// ============================================================
// cls token projection + CN2. grid BH, block 64
// ============================================================
__global__ void clsproj_kernel(const float* __restrict__ x,
                               const float* __restrict__ Wq,
                               const float* __restrict__ bq) {
    int bh = blockIdx.x;
    int b_ = bh / HH, h_ = bh % HH;
    int d  = threadIdx.x;
    int j  = h_*DH + d;
    const float* xr = x  + (size_t)(b_*SS)*EE;
    const float* wr = Wq + (size_t)j*EE;
    float s = 0.f;
    for (int e = 0; e < EE; e += 4) {
        float4 xv = *(const float4*)(xr + e);
        float4 wv = *(const float4*)(wr + e);
        s += xv.x*wv.x + xv.y*wv.y + xv.z*wv.z + xv.w*wv.w;
    }
    s += bq[j];
    CVEC[bh*DH + d] = s;
    __shared__ float red[64];
    red[d] = s*s; __syncthreads();
    for (int o = 32; o > 0; o >>= 1) { if (d < o) red[d] += red[d+o]; __syncthreads(); }
    if (d == 0) CN2[bh] = fmaxf(red[0], EPSF);
}

// ============================================================
// per-row q stats: QN2 and CQ. grid BH*SQ/8, block 256
// ============================================================
__global__ void qstats_kernel() {
    int row  = blockIdx.x*8 + (threadIdx.x >> 5);
    int lane = threadIdx.x & 31;
    int bh   = row >> 10;
    const float* qr = QS   + (size_t)row*DH;
    const float* cv = CVEC + bh*DH;
    float n2 = 0.f, cq = 0.f;
    #pragma unroll
    for (int d = lane; d < DH; d += 32) {
        float qv = qr[d];
        n2 += qv*qv;
        cq += qv*cv[d];
    }
    #pragma unroll
    for (int o = 16; o > 0; o >>= 1) {
        n2 += __shfl_xor_sync(0xffffffffu, n2, o);
        cq += __shfl_xor_sync(0xffffffffu, cq, o);
    }
    if (lane == 0) { QN2[row] = fmaxf(n2, EPSF); CQg[row] = cq; }
}

// ============================================================
// cls path: ck softmax -> cls_out row (fp16 into VALS). grid BH, block 256
// ============================================================
__global__ void cls_kernel() {
    int bh = blockIdx.x;
    int tid = threadIdx.x;
    const float* Kp = KS + (size_t)bh*SQ*DH;
    const float* Vp = VS + (size_t)bh*SQ*DH;
    __shared__ float p_s[SQ];
    __shared__ float red[256];
    __shared__ float c_s[DH];
    if (tid < DH) c_s[tid] = CVEC[bh*DH + tid];
    __syncthreads();

    float scale = rsqrtf(64.0f * CN2[bh]);
    float lo[4];
    #pragma unroll
    for (int p = 0; p < 4; p++) {
        int j = tid + p*256;
        const float* kr = Kp + (size_t)j*DH;
        float s = 0.f;
        #pragma unroll
        for (int d = 0; d < DH; d += 4) {
            float4 kv = *(const float4*)(kr + d);
            s += c_s[d]*kv.x + c_s[d+1]*kv.y + c_s[d+2]*kv.z + c_s[d+3]*kv.w;
        }
        lo[p] = s * scale;
    }
    float m = fmaxf(fmaxf(lo[0],lo[1]), fmaxf(lo[2],lo[3]));
    red[tid] = m; __syncthreads();
    #pragma unroll
    for (int o = 128; o > 0; o >>= 1) { if (tid < o) red[tid] = fmaxf(red[tid], red[tid+o]); __syncthreads(); }
    m = red[0]; __syncthreads();
    float e[4], s = 0.f;
    #pragma unroll
    for (int p = 0; p < 4; p++) { e[p] = __expf(lo[p] - m); s += e[p]; }
    red[tid] = s; __syncthreads();
    #pragma unroll
    for (int o = 128; o > 0; o >>= 1) { if (tid < o) red[tid] += red[tid+o]; __syncthreads(); }
    float inv = 1.0f / red[0]; __syncthreads();
    #pragma unroll
    for (int p = 0; p < 4; p++) p_s[tid + p*256] = e[p]*inv;
    __syncthreads();

    int d = tid & 63, g = tid >> 6;
    float acc = 0.f;
    for (int j = g*256; j < (g+1)*256; j++) acc += p_s[j] * Vp[(size_t)j*DH + d];
    red[tid] = acc; __syncthreads();
    if (g == 0) {
        float rsum = red[tid] + red[tid+64] + red[tid+128] + red[tid+192];
        int b_ = bh / HH, h_ = bh % HH;
        size_t idx = (size_t)(b_*SS)*EE + h_*DH + d;
        VALSh[idx] = __float2half(rsum);
    }
}

extern "C" void kernel_launch(void* const* d_in, const int* in_sizes, int n_in,
                              void* d_out, int out_size) {
    const float* x  = (const float*)d_in[0];
    const float* Wq = (const float*)d_in[1];
    const float* bq = (const float*)d_in[2];
    const float* Wk = (const float*)d_in[3];
    const float* bk = (const float*)d_in[4];
    const float* Wv = (const float*)d_in[5];
    const float* bv = (const float*)d_in[6];
    const float* Wo = (const float*)d_in[7];
    const float* bo = (const float*)d_in[8];
    const float* Wc = (const float*)d_in[9];
    const float* bc = (const float*)d_in[10];

    float* out  = (float*)d_out;
    float* attn = out + (size_t)BB*SS*EE;

    cudaFuncSetAttribute(proj_mm,    cudaFuncAttributeMaxDynamicSharedMemorySize, 40960);
    cudaFuncSetAttribute(out_mm,     cudaFuncAttributeMaxDynamicSharedMemorySize, 40960);
    cudaFuncSetAttribute(fused_attn, cudaFuncAttributeMaxDynamicSharedMemorySize, 81920);
    cudaFuncSetAttribute(proj_mm,    cudaFuncAttributePreferredSharedMemoryCarveout, 100);
    cudaFuncSetAttribute(out_mm,     cudaFuncAttributePreferredSharedMemoryCarveout, 100);
    cudaFuncSetAttribute(fused_attn, cudaFuncAttributePreferredSharedMemoryCarveout, 100);

    __half *xh, *wqh, *wkh, *wvh, *wch, *woh;
    cudaGetSymbolAddress((void**)&xh, Xh);
    cudaGetSymbolAddress((void**)&wqh, WqHh);
    cudaGetSymbolAddress((void**)&wkh, WkHh);
    cudaGetSymbolAddress((void**)&wvh, WvHh);
    cudaGetSymbolAddress((void**)&wch, WcHh);
    cudaGetSymbolAddress((void**)&woh, WoHh);

    int nx4 = BB*SS*EE/4, nw4 = EE*EE/4;
    // 1: x -> fp16
    convXh_kernel<<<(nx4+255)/256, 256>>>(x, xh, nx4);
    // 2: Wq + Wk -> fp16 x64
    convW2_kernel<<<dim3((nw4+255)/256, 2), 256>>>(Wq, wqh, Wk, wkh, nw4);
    // 3: Wv + Wc
    convW2_kernel<<<dim3((nw4+255)/256, 2), 256>>>(Wv, wvh, Wc, wch, nw4);
    // 4: proj (ncu capture target)
    proj_mm<<<dim3(8,32,4), 256, 40960>>>(bq, bk, bv, bc);
    // 5: Wo
    convW_kernel<<<(nw4+255)/256, 256>>>(Wo, woh, nw4);
    // 6-7: cls projection + q stats
    clsproj_kernel<<<BH, 64>>>(x, Wq, bq);
    qstats_kernel<<<BH*SQ/8, 256>>>();
    // 8: fused attention (stats -> QN2/QS dead scratch)
    fused_attn<<<dim3(8,BH), 256, 81920>>>(attn);
    // 9: attn normalization
    attn_fix<<<BH*SQ, 256>>>(attn);
    // 10: cls output row
    cls_kernel<<<BH, 256>>>();
    // 11: output projection
    out_mm<<<dim3(8,33), 256, 40960>>>(bo, out);
}

// round 16
// speedup vs baseline: 1.6635x; 1.0692x over previous
#include <cuda_runtime.h>
#include <cuda_bf16.h>
#include <cuda_fp16.h>
#include <cstdint>

#define BB 4
#define SS 1025
#define SQ 1024
#define EE 1024
#define HH 16
#define DH 64
#define BH (BB*HH)
#define EPSF 1e-5f
#define MROWS_OUT (BB*SS)     // 4100
#define MTILES_OUT 33         // 33*128 = 4224

typedef __nv_bfloat16 bf16;

// ---------------- device scratch (allocation-free) ----------------
// After fused_attn: QN2[row] = final row max (M), QS[row] = 1/rowsum (S).
__device__ float QS[BH*SQ*DH];          // fp32 q (qstats) -> later 1/rowsum
__device__ float KS[BH*SQ*DH];          // fp32 k  (cls path)
__device__ float VS[BH*SQ*DH];          // fp32 v  (cls path)
__device__ __half Xh[BB*SS*EE];                       // x single fp16
__device__ __half WqHh[EE*EE], WkHh[EE*EE];           // 64*W fp16 (single)
__device__ __half WvHh[EE*EE], WcHh[EE*EE];
__device__ __half WoHh[EE*EE];
__device__ __half Qh[BH*SQ*DH];                       // q single fp16
__device__ __half Kh16[BH*SQ*DH];                     // k single fp16
__device__ __half VTh[BH*DH*SQ];                      // V^T single fp16
__device__ __half CPTh[BH*DH*SQ];                     // cls_proj^T single fp16
__device__ __half VALSh[(size_t)MTILES_OUT*128*EE];   // values, single fp16
__device__ __half LOGh[(size_t)BH*SQ*SQ];             // raw logits staging (fp16)
__device__ float CVEC[BH*DH];
__device__ float CN2[BH];
__device__ float QN2[BH*SQ];            // |q|^2 -> later row max
__device__ float CQg[BH*SQ];

// ---------------- warp-mma helpers ----------------
__device__ __forceinline__ uint32_t s2u(const void* p) {
    uint32_t a;
    asm("{ .reg .u64 t; cvta.to.shared.u64 t, %1; cvt.u32.u64 %0, t; }" : "=r"(a) : "l"(p));
    return a;
}
#define LDSM4(R0,R1,R2,R3,addr) \
    asm volatile("ldmatrix.sync.aligned.m8n8.x4.shared.b16 {%0,%1,%2,%3}, [%4];" \
        : "=r"(R0),"=r"(R1),"=r"(R2),"=r"(R3) : "r"(addr))

__device__ __forceinline__ void mma16816h(float* c, uint32_t a0, uint32_t a1,
                                          uint32_t a2, uint32_t a3,
                                          uint32_t b0, uint32_t b1) {
    asm volatile(
        "mma.sync.aligned.m16n8k16.row.col.f32.f16.f16.f32 "
        "{%0,%1,%2,%3}, {%4,%5,%6,%7}, {%8,%9}, {%0,%1,%2,%3};"
        : "+f"(c[0]), "+f"(c[1]), "+f"(c[2]), "+f"(c[3])
        : "r"(a0), "r"(a1), "r"(a2), "r"(a3), "r"(b0), "r"(b1));
}

// fp16 single-pass k16 step: A single, B single. MT*16 x 32 warp tile.
template<int MT>
__device__ __forceinline__ void wmma_step1h(float (*acc)[4][4],
    uint32_t aB, uint32_t bB,
    int mrow0, int ncol0, int k0, int lane)
{
    uint32_t aF[MT][4];
    #pragma unroll
    for (int mi = 0; mi < MT; mi++) {
        uint32_t off = ((uint32_t)(mrow0 + mi*16 + (lane & 15))*40u + (uint32_t)k0 + ((lane >> 4) << 3)) * 2u;
        LDSM4(aF[mi][0], aF[mi][1], aF[mi][2], aF[mi][3], aB + off);
    }
    uint32_t bHf[4][2];
    int j = lane >> 3;
    #pragma unroll
    for (int p = 0; p < 2; p++) {
        uint32_t off = ((uint32_t)(ncol0 + p*16 + ((j >> 1) << 3) + (lane & 7))*40u + (uint32_t)k0 + ((j & 1) << 3)) * 2u;
        uint32_t r0, r1, r2, r3;
        LDSM4(r0, r1, r2, r3, bB + off);
        bHf[p*2][0] = r0; bHf[p*2][1] = r1; bHf[p*2+1][0] = r2; bHf[p*2+1][1] = r3;
    }
    #pragma unroll
    for (int mi = 0; mi < MT; mi++)
        #pragma unroll
        for (int nj = 0; nj < 4; nj++)
            mma16816h(acc[mi][nj], aF[mi][0], aF[mi][1], aF[mi][2], aF[mi][3], bHf[nj][0], bHf[nj][1]);
}

// 4 n8-frags (32 cols) from smem tile (stride 40)
__device__ __forceinline__ void ldB32(uint32_t (*bf)[2], uint32_t base, int n0_, int k0, int lane) {
    int j = lane >> 3;
    #pragma unroll
    for (int p = 0; p < 2; p++) {
        uint32_t off = ((uint32_t)(n0_ + p*16 + ((j >> 1) << 3) + (lane & 7))*40u + (uint32_t)k0 + ((j & 1) << 3)) * 2u;
        uint32_t r0, r1, r2, r3;
        LDSM4(r0, r1, r2, r3, base + off);
        bf[p*2][0] = r0; bf[p*2][1] = r1; bf[p*2+1][0] = r2; bf[p*2+1][1] = r3;
    }
}

// load nrows x 32 b16 elems into smem tile (stride 40 elems) via cp.async
__device__ __forceinline__ void ld_tile32(uint32_t sdst, const void* gv, size_t rstride, int nrows) {
    const __half* g = (const __half*)gv;
    int tid = threadIdx.x;
    int tot = nrows * 4;
    for (int u = tid; u < tot; u += 256) {
        int r = u >> 2, c = u & 3;
        uint32_t dst = sdst + (uint32_t)(r*80 + c*16);
        const __half* src = g + (size_t)r * rstride + (c << 3);
        asm volatile("cp.async.cg.shared.global [%0], [%1], 16;" :: "r"(dst), "l"(src) : "memory");
    }
}
#define CPA_COMMIT() asm volatile("cp.async.commit_group;" ::: "memory")
#define CPA_WAIT1()  asm volatile("cp.async.wait_group 1;" ::: "memory")
#define CPA_WAIT0()  asm volatile("cp.async.wait_group 0;" ::: "memory")

__device__ __forceinline__ uint32_t packh2(float a, float b) {
    __half2 t = __floats2half2_rn(a, b);
    return *(uint32_t*)&t;
}

// ============================================================
// conversions (fp32 -> single fp16; W scaled x64)
// ============================================================
__global__ void convXh_kernel(const float* __restrict__ s, __half* __restrict__ h, int n4) {
    int i = blockIdx.x * 256 + threadIdx.x;
    if (i >= n4) return;
    float4 v = ((const float4*)s)[i];
    uint2 hp;
    hp.x = packh2(v.x, v.y); hp.y = packh2(v.z, v.w);
    ((uint2*)h)[i] = hp;
}
// all five W tensors in one launch (blockIdx.y selects)
__global__ void convW5_kernel(const float* __restrict__ s0, const float* __restrict__ s1,
                              const float* __restrict__ s2, const float* __restrict__ s3,
                              const float* __restrict__ s4, int n4) {
    int i = blockIdx.x * 256 + threadIdx.x;
    if (i >= n4) return;
    int w = blockIdx.y;
    const float* s = (w==0)?s0:(w==1)?s1:(w==2)?s2:(w==3)?s3:s4;
    __half* h;
    if      (w == 0) h = WqHh;
    else if (w == 1) h = WkHh;
    else if (w == 2) h = WvHh;
    else if (w == 3) h = WcHh;
    else             h = WoHh;
    float4 v = ((const float4*)s)[i];
    uint2 hp;
    hp.x = packh2(v.x*64.f, v.y*64.f); hp.y = packh2(v.z*64.f, v.w*64.f);
    ((uint2*)h)[i] = hp;
}

// ============================================================
// proj: 128x128 tile of (x @ (64W)^T)/64 + b. fp16 single-pass. grid(8,32,4)
// ============================================================
__global__ void __launch_bounds__(256) proj_mm(
    const float* __restrict__ b0, const float* __restrict__ b1,
    const float* __restrict__ b2, const float* __restrict__ b3)
{
    extern __shared__ uint8_t dyn[];
    uint32_t sb = s2u(dyn);
    int tid = threadIdx.x, wid = tid >> 5, lane = tid & 31;

    int w = blockIdx.z;
    const __half* WHp = (w==0)?WqHh:(w==1)?WkHh:(w==2)?WvHh:WcHh;
    const float* bias = (w==0)?b0:(w==1)?b1:(w==2)?b2:b3;

    int m0 = blockIdx.y * 128, n0 = blockIdx.x * 128;
    int b_ = m0 >> 10, i0 = m0 & 1023;

    const __half* aF = Xh + (size_t)(b_*SS + i0 + 1)*EE;
    const __half* bH = WHp + (size_t)n0*EE;

    float acc[4][4][4] = {};
    int wm = wid & 1, wn = wid >> 1;
    int mrow0 = wm*64, ncol0 = wn*32;

    ld_tile32(sb,         aF, EE, 128);
    ld_tile32(sb + 10240, bH, EE, 128);
    CPA_COMMIT();
    int buf = 0;
    for (int ch = 0; ch < 32; ch++) {
        if (ch + 1 < 32) {
            uint32_t nb = sb + (buf^1)*20480;
            int kt = (ch + 1) * 32;
            ld_tile32(nb,         aF + kt, EE, 128);
            ld_tile32(nb + 10240, bH + kt, EE, 128);
            CPA_COMMIT();
            CPA_WAIT1();
        } else CPA_WAIT0();
        __syncthreads();
        uint32_t base = sb + buf*20480;
        wmma_step1h<4>(acc, base, base+10240, mrow0, ncol0, 0,  lane);
        wmma_step1h<4>(acc, base, base+10240, mrow0, ncol0, 16, lane);
        __syncthreads();
        buf ^= 1;
    }

    int rbase = mrow0 + (lane >> 2);
    int cbase = ncol0 + (lane & 3)*2;
    const float inv64 = 1.0f/64.0f;
    #pragma unroll
    for (int mi = 0; mi < 4; mi++)
        #pragma unroll
        for (int half = 0; half < 2; half++) {
            int i = i0 + rbase + mi*16 + half*8;
            #pragma unroll
            for (int nj = 0; nj < 4; nj++) {
                int col = n0 + cbase + nj*8;
                int h2 = col >> 6, d2 = col & 63;
                float v0 = acc[mi][nj][half*2]*inv64   + bias[col];
                float v1 = acc[mi][nj][half*2+1]*inv64 + bias[col+1];
                size_t qi = ((size_t)(b_*HH + h2)*SQ + i)*DH + d2;
                size_t ti = ((size_t)(b_*HH + h2)*DH + d2)*SQ + i;
                if (w == 0) {
                    *(float2*)&QS[qi] = make_float2(v0, v1);
                    *(uint32_t*)&Qh[qi] = packh2(v0, v1);
                } else if (w == 1) {
                    *(float2*)&KS[qi] = make_float2(v0, v1);
                    *(uint32_t*)&Kh16[qi] = packh2(v0, v1);
                } else if (w == 2) {
                    *(float2*)&VS[qi] = make_float2(v0, v1);
                    VTh[ti] = __float2half(v0);
                    VTh[ti + SQ] = __float2half(v1);
                } else {
                    CPTh[ti] = __float2half(v0);
                    CPTh[ti + SQ] = __float2half(v1);
                }
            }
        }
}

// ============================================================
// fused attention: S = Qh·Kh -> raw l to LOGh (fp16), dual online softmax,
// O1 += P1@V, O2 += P2@CP. grid(8,64) block 256.
// smem: Q 20480 + 2 x 30720 = 81920
// ============================================================
__global__ void __launch_bounds__(256) fused_attn()
{
    extern __shared__ uint8_t dyn[];
    uint32_t sQ = s2u(dyn);
    uint32_t sT = sQ + 20480;
    int tid = threadIdx.x, wid = tid >> 5, lane = tid & 31;
    int bh = blockIdx.y;
    int m0 = blockIdx.x * 128;
    int mrow0 = wid * 16;
    int g = lane >> 2, tig = lane & 3;
    int r0 = mrow0 + g, r1 = r0 + 8;
    int gr0 = m0 + r0, gr1 = m0 + r1;

    float qn0 = QN2[(size_t)bh*SQ + gr0], qn1 = QN2[(size_t)bh*SQ + gr1];
    float cn = CN2[bh];
    float sc0 = rsqrtf(64.0f * qn0), sc1r = rsqrtf(64.0f * qn1);
    float rr0 = rsqrtf(qn0 * cn), rr1 = rsqrtf(qn1 * cn);

    __half* logb = LOGh + (size_t)bh*SQ*SQ;
    const float* cqrow = CQg + (size_t)bh*SQ;

    {
        const __half* qh = Qh + (size_t)bh*SQ*DH + (size_t)m0*DH;
        ld_tile32(sQ,         qh,      DH, 128);
        ld_tile32(sQ + 10240, qh + 32, DH, 128);
        CPA_COMMIT();
    }

    #define FLOAD(bb, jt) do { \
        int j0_ = (jt) * 64; \
        const __half* kh_ = Kh16 + (size_t)bh*SQ*DH + (size_t)j0_*DH; \
        const __half* vh_ = VTh + (size_t)bh*DH*SQ + j0_; \
        const __half* ph_ = CPTh + (size_t)bh*DH*SQ + j0_; \
        ld_tile32((bb),        kh_,      DH, 64); \
        ld_tile32((bb)+5120,   kh_ + 32, DH, 64); \
        ld_tile32((bb)+10240,  vh_,      SQ, 64); \
        ld_tile32((bb)+15360,  vh_ + 32, SQ, 64); \
        ld_tile32((bb)+20480,  ph_,      SQ, 64); \
        ld_tile32((bb)+25600,  ph_ + 32, SQ, 64); \
        CPA_COMMIT(); \
    } while (0)

    float O1[8][4] = {}, O2[8][4] = {};
    float m1_0 = -1e30f, m1_1 = -1e30f, m2_0 = -1e30f, m2_1 = -1e30f;
    float s1_0 = 0.f, s1_1 = 0.f, s2_0 = 0.f, s2_1 = 0.f;

    FLOAD(sT, 0);
    int buf = 0;
    for (int jt = 0; jt < 16; jt++) {
        if (jt + 1 < 16) { FLOAD(sT + (buf^1)*30720, jt + 1); CPA_WAIT1(); }
        else CPA_WAIT0();
        __syncthreads();
        uint32_t bb = sT + buf*30720;
        int j0 = jt * 64;

        // ---- S = Qh · Kh ----
        float S[8][4] = {};
        #pragma unroll
        for (int kk = 0; kk < 64; kk += 16) {
            int cch = kk >> 5, k0 = kk & 16;
            uint32_t aQ = sQ + cch*10240;
            uint32_t a0, a1, a2, a3;
            uint32_t offA = ((uint32_t)(mrow0 + (lane & 15))*40u + (uint32_t)k0 + ((lane >> 4) << 3)) * 2u;
            LDSM4(a0, a1, a2, a3, aQ + offA);
            uint32_t bHf[4][2], bHf2[4][2];
            uint32_t kb = bb + cch*5120;
            ldB32(bHf,  kb, 0,  k0, lane);
            ldB32(bHf2, kb, 32, k0, lane);
            #pragma unroll
            for (int f = 0; f < 4; f++) {
                mma16816h(S[f],   a0, a1, a2, a3, bHf[f][0],  bHf[f][1]);
                mma16816h(S[f+4], a0, a1, a2, a3, bHf2[f][0], bHf2[f][1]);
            }
        }

        // ---- scale to l, store raw (fp16), track maxes ----
        float cqv[8][2];
        float lmax0 = -1e30f, lmax1 = -1e30f, l2max0 = -1e30f, l2max1 = -1e30f;
        #pragma unroll
        for (int f = 0; f < 8; f++) {
            int col = j0 + f*8 + tig*2;
            float2 cq = *(const float2*)&cqrow[col];
            cqv[f][0] = cq.x; cqv[f][1] = cq.y;
            S[f][0] *= sc0;  S[f][1] *= sc0;
            S[f][2] *= sc1r; S[f][3] *= sc1r;
            *(uint32_t*)&logb[(size_t)gr0*SQ + col] = packh2(S[f][0], S[f][1]);
            *(uint32_t*)&logb[(size_t)gr1*SQ + col] = packh2(S[f][2], S[f][3]);
            lmax0 = fmaxf(lmax0, fmaxf(S[f][0], S[f][1]));
            lmax1 = fmaxf(lmax1, fmaxf(S[f][2], S[f][3]));
            l2max0 = fmaxf(l2max0, fmaxf(S[f][0]*cq.x*rr0, S[f][1]*cq.y*rr0));
            l2max1 = fmaxf(l2max1, fmaxf(S[f][2]*cq.x*rr1, S[f][3]*cq.y*rr1));
        }
        #pragma unroll
        for (int o = 1; o <= 2; o <<= 1) {
            lmax0  = fmaxf(lmax0,  __shfl_xor_sync(0xffffffffu, lmax0,  o));
            lmax1  = fmaxf(lmax1,  __shfl_xor_sync(0xffffffffu, lmax1,  o));
            l2max0 = fmaxf(l2max0, __shfl_xor_sync(0xffffffffu, l2max0, o));
            l2max1 = fmaxf(l2max1, __shfl_xor_sync(0xffffffffu, l2max1, o));
        }
        float m1n0 = fmaxf(m1_0, lmax0),  m1n1 = fmaxf(m1_1, lmax1);
        float m2n0 = fmaxf(m2_0, l2max0), m2n1 = fmaxf(m2_1, l2max1);
        float f10 = __expf(m1_0 - m1n0), f11 = __expf(m1_1 - m1n1);
        float f20 = __expf(m2_0 - m2n0), f21 = __expf(m2_1 - m2n1);
        m1_0 = m1n0; m1_1 = m1n1; m2_0 = m2n0; m2_1 = m2n1;
        #pragma unroll
        for (int f = 0; f < 8; f++) {
            O1[f][0] *= f10; O1[f][1] *= f10; O1[f][2] *= f11; O1[f][3] *= f11;
            O2[f][0] *= f20; O2[f][1] *= f20; O2[f][2] *= f21; O2[f][3] *= f21;
        }

        // ---- path 1: O1 += P1 @ V ----
        {
            uint32_t ph01[8], ph23[8];
            float ps0 = 0.f, ps1 = 0.f;
            #pragma unroll
            for (int f = 0; f < 8; f++) {
                float p0 = __expf(S[f][0] - m1n0), p1v = __expf(S[f][1] - m1n0);
                float p2v = __expf(S[f][2] - m1n1), p3v = __expf(S[f][3] - m1n1);
                ps0 += p0 + p1v; ps1 += p2v + p3v;
                ph01[f] = packh2(p0, p1v);
                ph23[f] = packh2(p2v, p3v);
            }
            #pragma unroll
            for (int o = 1; o <= 2; o <<= 1) {
                ps0 += __shfl_xor_sync(0xffffffffu, ps0, o);
                ps1 += __shfl_xor_sync(0xffffffffu, ps1, o);
            }
            s1_0 = s1_0 * f10 + ps0; s1_1 = s1_1 * f11 + ps1;
            #pragma unroll
            for (int kk = 0; kk < 64; kk += 16) {
                int cch = kk >> 5, k0 = kk & 16;
                int gp = kk >> 3;
                uint32_t vb = bb + 10240 + cch*5120;
                uint32_t bHf[4][2], bHf2[4][2];
                ldB32(bHf,  vb, 0,  k0, lane);
                ldB32(bHf2, vb, 32, k0, lane);
                uint32_t a0 = ph01[gp], a1 = ph23[gp], a2 = ph01[gp+1], a3 = ph23[gp+1];
                #pragma unroll
                for (int f = 0; f < 4; f++) {
                    mma16816h(O1[f],   a0, a1, a2, a3, bHf[f][0],  bHf[f][1]);
                    mma16816h(O1[f+4], a0, a1, a2, a3, bHf2[f][0], bHf2[f][1]);
                }
            }
        }

        // ---- path 2: O2 += P2 @ CP ----
        {
            uint32_t ph01[8], ph23[8];
            float ps0 = 0.f, ps1 = 0.f;
            #pragma unroll
            for (int f = 0; f < 8; f++) {
                float p0 = __expf(S[f][0]*cqv[f][0]*rr0 - m2n0);
                float p1v = __expf(S[f][1]*cqv[f][1]*rr0 - m2n0);
                float p2v = __expf(S[f][2]*cqv[f][0]*rr1 - m2n1);
                float p3v = __expf(S[f][3]*cqv[f][1]*rr1 - m2n1);
                ps0 += p0 + p1v; ps1 += p2v + p3v;
                ph01[f] = packh2(p0, p1v);
                ph23[f] = packh2(p2v, p3v);
            }
            #pragma unroll
            for (int o = 1; o <= 2; o <<= 1) {
                ps0 += __shfl_xor_sync(0xffffffffu, ps0, o);
                ps1 += __shfl_xor_sync(0xffffffffu, ps1, o);
            }
            s2_0 = s2_0 * f20 + ps0; s2_1 = s2_1 * f21 + ps1;
            #pragma unroll
            for (int kk = 0; kk < 64; kk += 16) {
                int cch = kk >> 5, k0 = kk & 16;
                int gp = kk >> 3;
                uint32_t pb = bb + 20480 + cch*5120;
                uint32_t bHf[4][2], bHf2[4][2];
                ldB32(bHf,  pb, 0,  k0, lane);
                ldB32(bHf2, pb, 32, k0, lane);
                uint32_t a0 = ph01[gp], a1 = ph23[gp], a2 = ph01[gp+1], a3 = ph23[gp+1];
                #pragma unroll
                for (int f = 0; f < 4; f++) {
                    mma16816h(O2[f],   a0, a1, a2, a3, bHf[f][0],  bHf[f][1]);
                    mma16816h(O2[f+4], a0, a1, a2, a3, bHf2[f][0], bHf2[f][1]);
                }
            }
        }
        __syncthreads();
        buf ^= 1;
    }
    #undef FLOAD

    // ---- epilogue: values rows + stats into dead scratch ----
    int b_ = bh / HH, h_ = bh % HH;
    float is10 = 1.f/s1_0, is11 = 1.f/s1_1, is20 = 1.f/s2_0, is21 = 1.f/s2_1;
    size_t ob0 = (size_t)(b_*SS + 1 + gr0)*EE + h_*DH;
    size_t ob1 = (size_t)(b_*SS + 1 + gr1)*EE + h_*DH;
    #pragma unroll
    for (int f = 0; f < 8; f++) {
        int d = f*8 + tig*2;
        float v0 = O1[f][0]*is10 + O2[f][0]*is20;
        float v1 = O1[f][1]*is10 + O2[f][1]*is20;
        float v2 = O1[f][2]*is11 + O2[f][2]*is21;
        float v3 = O1[f][3]*is11 + O2[f][3]*is21;
        *(uint32_t*)&VALSh[ob0 + d] = packh2(v0, v1);
        *(uint32_t*)&VALSh[ob1 + d] = packh2(v2, v3);
    }
    if (tig == 0) {
        QN2[(size_t)bh*SQ + gr0] = m1_0; QS[(size_t)bh*SQ + gr0] = is10;
        QN2[(size_t)bh*SQ + gr1] = m1_1; QS[(size_t)bh*SQ + gr1] = is11;
    }
}

// ============================================================
// attn_fix: attn = exp(l - M)/S from fp16 LOGh into fp32 d_out.
// one row per block, 4 elems/thread.
// ============================================================
__global__ void attn_fix(float* __restrict__ attn) {
    int row = blockIdx.x;
    float m = QN2[row], si = QS[row];
    const uint2* src = (const uint2*)(LOGh + (size_t)row*SQ);
    float4* dst = (float4*)(attn + (size_t)row*SQ);
    uint2 lv = src[threadIdx.x];
    __half2 h0 = *(__half2*)&lv.x;
    __half2 h1 = *(__half2*)&lv.y;
    float4 v;
    v.x = __expf(__half2float(h0.x) - m)*si;
    v.y = __expf(__half2float(h0.y) - m)*si;
    v.z = __expf(__half2float(h1.x) - m)*si;
    v.w = __expf(__half2float(h1.y) - m)*si;
    dst[threadIdx.x] = v;
}

// ============================================================
// out: VALS(f16) @ (64Wo)^T/64 + bo. fp16 single-pass. grid(8,33)
// ============================================================
__global__ void __launch_bounds__(256) out_mm(const float* __restrict__ bo,
                                             float* __restrict__ out)
{
    extern __shared__ uint8_t dyn[];
    uint32_t sb = s2u(dyn);
    int tid = threadIdx.x, wid = tid >> 5, lane = tid & 31;
    int m0 = blockIdx.y * 128, n0 = blockIdx.x * 128;

    const __half* aF = VALSh + (size_t)m0*EE;
    const __half* bH = WoHh + (size_t)n0*EE;

    float acc[4][4][4] = {};
    int wm = wid & 1, wn = wid >> 1;
    int mrow0 = wm*64, ncol0 = wn*32;

    ld_tile32(sb,         aF, EE, 128);
    ld_tile32(sb + 10240, bH, EE, 128);
    CPA_COMMIT();
    int buf = 0;
    for (int ch = 0; ch < 32; ch++) {
        if (ch + 1 < 32) {
            uint32_t nb = sb + (buf^1)*20480;
            int kt = (ch + 1) * 32;
            ld_tile32(nb,         aF + kt, EE, 128);
            ld_tile32(nb + 10240, bH + kt, EE, 128);
            CPA_COMMIT();
            CPA_WAIT1();
        } else CPA_WAIT0();
        __syncthreads();
        uint32_t base = sb + buf*20480;
        wmma_step1h<4>(acc, base, base+10240, mrow0, ncol0, 0,  lane);
        wmma_step1h<4>(acc, base, base+10240, mrow0, ncol0, 16, lane);
        __syncthreads();
        buf ^= 1;
    }

    int rbase = mrow0 + (lane >> 2);
    int cbase = ncol0 + (lane & 3)*2;
    const float inv64 = 1.0f/64.0f;
    #pragma unroll
    for (int mi = 0; mi < 4; mi++)
        #pragma unroll
        for (int half = 0; half < 2; half++) {
            int mr = m0 + rbase + mi*16 + half*8;
            if (mr >= MROWS_OUT) continue;
            #pragma unroll
            for (int nj = 0; nj < 4; nj++) {
                int col = n0 + cbase + nj*8;
                *(float2*)&out[(size_t)mr*EE + col] =
                    make_float2(acc[mi][nj][half*2]*inv64 + bo[col],
                                acc[mi][nj][half*2+1]*inv64 + bo[col+1]);
            }
        }
}

// ============================================================
// cls token projection + CN2. grid BH, block 64
// ============================================================
__global__ void clsproj_kernel(const float* __restrict__ x,
                               const float* __restrict__ Wq,
                               const float* __restrict__ bq) {
    int bh = blockIdx.x;
    int b_ = bh / HH, h_ = bh % HH;
    int d  = threadIdx.x;
    int j  = h_*DH + d;
    const float* xr = x  + (size_t)(b_*SS)*EE;
    const float* wr = Wq + (size_t)j*EE;
    float s = 0.f;
    for (int e = 0; e < EE; e += 4) {
        float4 xv = *(const float4*)(xr + e);
        float4 wv = *(const float4*)(wr + e);
        s += xv.x*wv.x + xv.y*wv.y + xv.z*wv.z + xv.w*wv.w;
    }
    s += bq[j];
    CVEC[bh*DH + d] = s;
    __shared__ float red[64];
    red[d] = s*s; __syncthreads();
    for (int o = 32; o > 0; o >>= 1) { if (d < o) red[d] += red[d+o]; __syncthreads(); }
    if (d == 0) CN2[bh] = fmaxf(red[0], EPSF);
}

// ============================================================
// per-row q stats: QN2 and CQ. grid BH*SQ/8, block 256
// ============================================================
__global__ void qstats_kernel() {
    int row  = blockIdx.x*8 + (threadIdx.x >> 5);
    int lane = threadIdx.x & 31;
    int bh   = row >> 10;
    const float* qr = QS   + (size_t)row*DH;
    const float* cv = CVEC + bh*DH;
    float n2 = 0.f, cq = 0.f;
    #pragma unroll
    for (int d = lane; d < DH; d += 32) {
        float qv = qr[d];
        n2 += qv*qv;
        cq += qv*cv[d];
    }
    #pragma unroll
    for (int o = 16; o > 0; o >>= 1) {
        n2 += __shfl_xor_sync(0xffffffffu, n2, o);
        cq += __shfl_xor_sync(0xffffffffu, cq, o);
    }
    if (lane == 0) { QN2[row] = fmaxf(n2, EPSF); CQg[row] = cq; }
}

// ============================================================
// cls path: ck softmax -> cls_out row (fp16 into VALS). grid BH, block 256
// ============================================================
__global__ void cls_kernel() {
    int bh = blockIdx.x;
    int tid = threadIdx.x;
    const float* Kp = KS + (size_t)bh*SQ*DH;
    const float* Vp = VS + (size_t)bh*SQ*DH;
    __shared__ float p_s[SQ];
    __shared__ float red[256];
    __shared__ float c_s[DH];
    if (tid < DH) c_s[tid] = CVEC[bh*DH + tid];
    __syncthreads();

    float scale = rsqrtf(64.0f * CN2[bh]);
    float lo[4];
    #pragma unroll
    for (int p = 0; p < 4; p++) {
        int j = tid + p*256;
        const float* kr = Kp + (size_t)j*DH;
        float s = 0.f;
        #pragma unroll
        for (int d = 0; d < DH; d += 4) {
            float4 kv = *(const float4*)(kr + d);
            s += c_s[d]*kv.x + c_s[d+1]*kv.y + c_s[d+2]*kv.z + c_s[d+3]*kv.w;
        }
        lo[p] = s * scale;
    }
    float m = fmaxf(fmaxf(lo[0],lo[1]), fmaxf(lo[2],lo[3]));
    red[tid] = m; __syncthreads();
    #pragma unroll
    for (int o = 128; o > 0; o >>= 1) { if (tid < o) red[tid] = fmaxf(red[tid], red[tid+o]); __syncthreads(); }
    m = red[0]; __syncthreads();
    float e[4], s = 0.f;
    #pragma unroll
    for (int p = 0; p < 4; p++) { e[p] = __expf(lo[p] - m); s += e[p]; }
    red[tid] = s; __syncthreads();
    #pragma unroll
    for (int o = 128; o > 0; o >>= 1) { if (tid < o) red[tid] += red[tid+o]; __syncthreads(); }
    float inv = 1.0f / red[0]; __syncthreads();
    #pragma unroll
    for (int p = 0; p < 4; p++) p_s[tid + p*256] = e[p]*inv;
    __syncthreads();

    int d = tid & 63, g = tid >> 6;
    float acc = 0.f;
    for (int j = g*256; j < (g+1)*256; j++) acc += p_s[j] * Vp[(size_t)j*DH + d];
    red[tid] = acc; __syncthreads();
    if (g == 0) {
        float rsum = red[tid] + red[tid+64] + red[tid+128] + red[tid+192];
        int b_ = bh / HH, h_ = bh % HH;
        size_t idx = (size_t)(b_*SS)*EE + h_*DH + d;
        VALSh[idx] = __float2half(rsum);
    }
}

extern "C" void kernel_launch(void* const* d_in, const int* in_sizes, int n_in,
                              void* d_out, int out_size) {
    const float* x  = (const float*)d_in[0];
    const float* Wq = (const float*)d_in[1];
    const float* bq = (const float*)d_in[2];
    const float* Wk = (const float*)d_in[3];
    const float* bk = (const float*)d_in[4];
    const float* Wv = (const float*)d_in[5];
    const float* bv = (const float*)d_in[6];
    const float* Wo = (const float*)d_in[7];
    const float* bo = (const float*)d_in[8];
    const float* Wc = (const float*)d_in[9];
    const float* bc = (const float*)d_in[10];

    float* out  = (float*)d_out;
    float* attn = out + (size_t)BB*SS*EE;

    cudaFuncSetAttribute(proj_mm,    cudaFuncAttributeMaxDynamicSharedMemorySize, 40960);
    cudaFuncSetAttribute(out_mm,     cudaFuncAttributeMaxDynamicSharedMemorySize, 40960);
    cudaFuncSetAttribute(fused_attn, cudaFuncAttributeMaxDynamicSharedMemorySize, 81920);
    cudaFuncSetAttribute(proj_mm,    cudaFuncAttributePreferredSharedMemoryCarveout, 100);
    cudaFuncSetAttribute(out_mm,     cudaFuncAttributePreferredSharedMemoryCarveout, 100);
    cudaFuncSetAttribute(fused_attn, cudaFuncAttributePreferredSharedMemoryCarveout, 100);

    __half* xh;
    cudaGetSymbolAddress((void**)&xh, Xh);

    int nx4 = BB*SS*EE/4, nw4 = EE*EE/4;
    // 1: x -> fp16
    convXh_kernel<<<(nx4+255)/256, 256>>>(x, xh, nx4);
    // 2: all five W -> fp16 x64 (one launch)
    convW5_kernel<<<dim3((nw4+255)/256, 5), 256>>>(Wq, Wk, Wv, Wc, Wo, nw4);
    // 3: cls projection (independent of conversions)
    clsproj_kernel<<<BH, 64>>>(x, Wq, bq);
    // 4: proj (ncu capture target)
    proj_mm<<<dim3(8,32,4), 256, 40960>>>(bq, bk, bv, bc);
    // 5: q stats
    qstats_kernel<<<BH*SQ/8, 256>>>();
    // 6: fused attention (raw logits -> LOGh fp16; stats -> QN2/QS)
    fused_attn<<<dim3(8,BH), 256, 81920>>>();
    // 7: attn normalization (fp16 -> fp32 d_out)
    attn_fix<<<BH*SQ, 256>>>(attn);
    // 8: cls output row
    cls_kernel<<<BH, 256>>>();
    // 9: output projection
    out_mm<<<dim3(8,33), 256, 40960>>>(bo, out);
}